// round 14
// baseline (speedup 1.0000x reference)
#include <cuda_runtime.h>
#include <cuda_fp16.h>
#include <cuda_fp8.h>
#include <math_constants.h>
#include <cstdint>

// ---------------- problem constants ----------------
#define BATCH   8
#define EMB     768
#define LSEQ    2304
#define NHEAD   12
#define HDIM    64
#define MROWS   (LSEQ*BATCH)          // 18432
#define NHEADS_TOT (BATCH*NHEAD)      // 96
#define KCH     12                    // fp16 K chunks of 64
#define KCH8    6                     // fp8 K chunks of 128
#define MT      (MROWS/128)           // 144 GEMM M-tiles
#define NSEG    4
#define LSEG    (LSEQ/NSEG)           // 576

// fp16 tile: 128 rows x 72 fp16 (144B pitch) = 18432 B
// fp8  tile: 128 rows x 144 B pitch (128 data + 16 pad) = 18432 B
#define TILE_PAD    9216
#define TILE_B      18432
#define SMEM_DATA   110592            // 3 stages x 2 tiles
#define GEMM_SMEM   (SMEM_DATA + 128)

#define SCALE_X 16.0f
#define SCALE_W 64.0f
#define INV_SCALE (1.0f/(SCALE_X*SCALE_W))

typedef unsigned long long u64t;

// ---------------- PTX helpers ----------------
__device__ __forceinline__ uint32_t smem_to_u32(const void* p) {
    uint32_t a;
    asm("{ .reg .u64 t; cvta.to.shared.u64 t, %1; cvt.u32.u64 %0, t; }" : "=r"(a) : "l"(p));
    return a;
}
__device__ __forceinline__ void ldsm4(uint32_t* r, uint32_t addr) {
    asm volatile("ldmatrix.sync.aligned.m8n8.x4.shared.b16 {%0,%1,%2,%3}, [%4];"
        : "=r"(r[0]), "=r"(r[1]), "=r"(r[2]), "=r"(r[3]) : "r"(addr));
}
__device__ __forceinline__ void ldsm4t(uint32_t* r, uint32_t addr) {
    asm volatile("ldmatrix.sync.aligned.m8n8.x4.trans.shared.b16 {%0,%1,%2,%3}, [%4];"
        : "=r"(r[0]), "=r"(r[1]), "=r"(r[2]), "=r"(r[3]) : "r"(addr));
}
__device__ __forceinline__ void mma16816(float* c, const uint32_t* a, uint32_t b0, uint32_t b1) {
    asm volatile("mma.sync.aligned.m16n8k16.row.col.f32.f16.f16.f32 "
        "{%0,%1,%2,%3}, {%4,%5,%6,%7}, {%8,%9}, {%0,%1,%2,%3};"
        : "+f"(c[0]), "+f"(c[1]), "+f"(c[2]), "+f"(c[3])
        : "r"(a[0]), "r"(a[1]), "r"(a[2]), "r"(a[3]), "r"(b0), "r"(b1));
}
__device__ __forceinline__ void mma16832e4(float* c, const uint32_t* a, uint32_t b0, uint32_t b1) {
    asm volatile("mma.sync.aligned.m16n8k32.row.col.f32.e4m3.e4m3.f32 "
        "{%0,%1,%2,%3}, {%4,%5,%6,%7}, {%8,%9}, {%0,%1,%2,%3};"
        : "+f"(c[0]), "+f"(c[1]), "+f"(c[2]), "+f"(c[3])
        : "r"(a[0]), "r"(a[1]), "r"(a[2]), "r"(a[3]), "r"(b0), "r"(b1));
}
#define MBARRIER_INIT(addr, cnt) \
    asm volatile("mbarrier.init.shared.b64 [%0], %1;" :: "r"((uint32_t)(addr)), "r"((uint32_t)(cnt)) : "memory")
#define MBARRIER_ARRIVE(addr) \
    asm volatile("mbarrier.arrive.shared.b64 _, [%0];" :: "r"((uint32_t)(addr)) : "memory")
#define MBARRIER_EXPECT_TX(addr, bytes) \
    asm volatile("mbarrier.arrive.expect_tx.shared.b64 _, [%0], %1;" :: "r"((uint32_t)(addr)), "r"((uint32_t)(bytes)) : "memory")
#define MBARRIER_WAIT_PARITY(mbar_smem_addr, phase_parity) do { \
    uint32_t _mbar = (uint32_t)(mbar_smem_addr); \
    uint32_t _parity = (uint32_t)(phase_parity); \
    uint32_t _done; \
    asm volatile("{\n\t.reg .pred p;\n\t" \
        "mbarrier.try_wait.parity.acquire.cta.shared::cta.b64 p, [%1], %2;\n\t" \
        "selp.b32 %0, 1, 0, p;\n\t}" \
        : "=r"(_done) : "r"(_mbar), "r"(_parity) : "memory"); \
    if (!_done) { \
        asm volatile("{\n\t.reg .pred P1;\n\t" \
            "WAIT_LOOP_%=:\n\t" \
            "mbarrier.try_wait.parity.acquire.cta.shared::cta.b64 P1, [%0], %1, 0x989680;\n\t" \
            "@P1 bra.uni WAIT_DONE_%=;\n\t" \
            "bra.uni WAIT_LOOP_%=;\n\t" \
            "WAIT_DONE_%=:\n\t}" \
            :: "r"(_mbar), "r"(_parity) : "memory"); \
    } \
} while(0)
__device__ __forceinline__ void bulk_g2s(uint32_t dst_smem, const void* gsrc, uint32_t bytes, uint32_t mbar) {
    asm volatile(
        "cp.async.bulk.shared::cluster.global.mbarrier::complete_tx::bytes [%0], [%1], %2, [%3];"
        :: "r"(dst_smem), "l"(gsrc), "r"(bytes), "r"(mbar) : "memory");
}

// ---------------- scratch globals ----------------
__device__ __align__(1024) __half d_Qh[MROWS*EMB];
__device__ __align__(1024) __half d_Kh[MROWS*EMB];
__device__ __align__(1024) __half d_Vh[MROWS*EMB];
__device__ __align__(1024) __half d_Xh[MT*KCH*TILE_PAD];        // fp16 tiled X (residual)
__device__ __align__(1024) unsigned char d_X8[MT*KCH8*TILE_B];  // fp8 tiled X (scaled)
__device__ __align__(1024) __half d_Yh[MT*KCH*TILE_PAD];
__device__ __align__(1024) unsigned char d_Wqkv8[18*KCH8*TILE_B]; // fp8 W (scaled)
__device__ __align__(1024) __half d_Wo[6*KCH*TILE_PAD];
__device__ float d_kvT[NSEG*NHEADS_TOT*64*128];
__device__ float d_ksum[NSEG*NHEADS_TOT*128];
__device__ __align__(16) __half d_kvTh[NHEADS_TOT*64*128];
__device__ float d_ksumR[NHEADS_TOT*128];

__device__ __forceinline__ uint32_t tiled_idx(int tile, int r, int k) {   // fp16 tiles
    return (uint32_t)tile * TILE_PAD + (uint32_t)r * 72u + (uint32_t)k;
}
__device__ __forceinline__ uint32_t tiled_idx8(int tile, int r, int kbyte) { // fp8 tiles
    return (uint32_t)tile * TILE_B + (uint32_t)r * 144u + (uint32_t)kbyte;
}
__device__ __forceinline__ unsigned char to_e4m3(float v) {
    return (unsigned char)__nv_cvt_float_to_fp8(v, __NV_SATFINITE, __NV_E4M3);
}

// ---------------- weight conversion (QKV -> fp8 scaled, Wo -> fp16) --------
__global__ void wconv_kernel(const float* __restrict__ Wq, const float* __restrict__ Wk,
                             const float* __restrict__ Wv, const float* __restrict__ Wo) {
    int which = blockIdx.y;
    const float* W = (which == 0) ? Wq : (which == 1) ? Wk : (which == 2) ? Wv : Wo;
    int idx = blockIdx.x * 256 + threadIdx.x;
    if (idx >= EMB * EMB) return;
    int n = idx / EMB, e = idx % EMB;
    if (which < 3) {
        uint32_t t = tiled_idx8((which * 6 + (n >> 7)) * KCH8 + (e >> 7), n & 127, e & 127);
        d_Wqkv8[t] = to_e4m3(W[idx] * SCALE_W);
    } else {
        uint32_t t = tiled_idx(((n >> 7)) * KCH + (e >> 6), n & 127, e & 63);
        d_Wo[t] = __float2half(W[idx]);
    }
}

// ---------------- transpose (B,E,L)->(L*B,E): fp16 + fp8 tiles --------------
__global__ void transpose_kernel(const float* __restrict__ q) {
    __shared__ float tile[32][33];
    int b  = blockIdx.z;
    int l0 = blockIdx.x * 32;
    int e0 = blockIdx.y * 32;
    int tx = threadIdx.x, ty = threadIdx.y;   // 32 x 8
    const float* src = q + (size_t)b * EMB * LSEQ;
    #pragma unroll
    for (int i = 0; i < 32; i += 8)
        tile[ty + i][tx] = src[(size_t)(e0 + ty + i) * LSEQ + l0 + tx];
    __syncthreads();
    #pragma unroll
    for (int i = 0; i < 32; i += 8) {
        int l = l0 + ty + i;
        int e = e0 + tx;
        int m = l * BATCH + b;
        float v = tile[tx][ty + i];
        d_Xh[tiled_idx((m >> 7) * KCH + (e >> 6), m & 127, e & 63)] = __float2half(v);
        d_X8[tiled_idx8((m >> 7) * KCH8 + (e >> 7), m & 127, e & 127)] = to_e4m3(v * SCALE_X);
    }
}

// ---------------- FP8 HMMA GEMM 128x128 tile (QKV), fp16 out ----------------
__global__ __launch_bounds__(128, 2) void tcgemm8_kernel(
    const unsigned char* __restrict__ A, const unsigned char* __restrict__ B,
    const float* __restrict__ b0p, const float* __restrict__ b1p, const float* __restrict__ b2p,
    __half* __restrict__ C0, __half* __restrict__ C1, __half* __restrict__ C2,
    int reluMask)
{
    constexpr int NST = 3;
    constexpr uint32_t STAGE_BYTES = 2 * TILE_B;

    extern __shared__ __align__(1024) char smem[];
    uint32_t sb = smem_to_u32(smem);
    int tid  = threadIdx.x;
    int lane = tid & 31, wid = tid >> 5;
    int nt = blockIdx.x, mt = blockIdx.y;
    int sel = nt / 6, ntc = nt % 6;
    const float* bias = (sel == 0) ? b0p : (sel == 1) ? b1p : b2p;
    __half* C = (sel == 0) ? C0 : (sel == 1) ? C1 : C2;
    int doRelu = (reluMask >> sel) & 1;
    int wm = wid & 1;
    int wn = wid >> 1;

    uint32_t mb_full  = sb + SMEM_DATA;
    uint32_t mb_empty = sb + SMEM_DATA + 48;

    if (tid == 0) {
        #pragma unroll
        for (int s = 0; s < NST; s++) {
            MBARRIER_INIT(mb_full + 8 * s, 1);
            MBARRIER_INIT(mb_empty + 8 * s, 128);
        }
        asm volatile("fence.proxy.async.shared::cta;" ::: "memory");
    }
    __syncthreads();

    const unsigned char* gA = A + (size_t)mt * KCH8 * TILE_B;
    const unsigned char* gB = B + (size_t)nt * KCH8 * TILE_B;

    int emptyPh[NST], fullPh[NST];
    #pragma unroll
    for (int s = 0; s < NST; s++) { emptyPh[s] = 1; fullPh[s] = 0; }

    auto produce = [&](int c) {
        if (tid == 0) {
            int s = c % NST;
            MBARRIER_WAIT_PARITY(mb_empty + 8 * s, emptyPh[s]);
            emptyPh[s] ^= 1;
            uint32_t dst = sb + s * STAGE_BYTES;
            uint32_t mbar = mb_full + 8 * s;
            MBARRIER_EXPECT_TX(mbar, STAGE_BYTES);
            bulk_g2s(dst,          gA + (size_t)c * TILE_B, TILE_B, mbar);
            bulk_g2s(dst + TILE_B, gB + (size_t)c * TILE_B, TILE_B, mbar);
        }
    };

    float acc[4][8][4];
    #pragma unroll
    for (int t = 0; t < 4; t++)
        #pragma unroll
        for (int j = 0; j < 8; j++)
            #pragma unroll
            for (int i = 0; i < 4; i++) acc[t][j][i] = 0.f;

    int a_mr = lane & 15;
    int a_ks = lane >> 4;
    int b_nr = ((lane >> 4) << 3) | (lane & 7);
    int b_ks = (lane >> 3) & 1;

    #pragma unroll
    for (int s = 0; s < NST; s++) produce(s);

    for (int c = 0; c < KCH8; c++) {
        int s = c % NST;
        MBARRIER_WAIT_PARITY(mb_full + 8 * s, fullPh[s]);
        fullPh[s] ^= 1;

        uint32_t stB = sb + s * STAGE_BYTES;
        uint32_t aRow0 = (uint32_t)(wm * 64);

        #pragma unroll
        for (int kc = 0; kc < 4; kc++) {   // 32 fp8 K-elems per step
            uint32_t ah[4][4], bb[4][4];
            #pragma unroll
            for (int t = 0; t < 4; t++) {
                uint32_t off = (aRow0 + t * 16 + a_mr) * 144u + kc * 32u + a_ks * 16u;
                ldsm4(ah[t], stB + off);
            }
            #pragma unroll
            for (int g = 0; g < 4; g++) {
                uint32_t off = (uint32_t)(wn * 64 + g * 16 + b_nr) * 144u + kc * 32u + b_ks * 16u;
                ldsm4(bb[g], stB + TILE_B + off);
            }
            #pragma unroll
            for (int t = 0; t < 4; t++)
                #pragma unroll
                for (int j = 0; j < 8; j++)
                    mma16832e4(acc[t][j], ah[t], bb[j >> 1][2 * (j & 1)], bb[j >> 1][2 * (j & 1) + 1]);
        }
        MBARRIER_ARRIVE(mb_empty + 8 * s);
        if (c + NST < KCH8) produce(c + NST);
    }

    // epilogue: rescale + bias (+relu), fp16 out
    int g = lane >> 2, tq = lane & 3;
    int mbase = mt * 128 + wm * 64;
    #pragma unroll
    for (int t = 0; t < 4; t++) {
        int r0 = mbase + t * 16 + g;
        #pragma unroll
        for (int j = 0; j < 8; j++) {
            int col = ntc * 128 + wn * 64 + j * 8 + tq * 2;
            float b0 = __ldg(&bias[col]), b1 = __ldg(&bias[col + 1]);
            float v0 = acc[t][j][0] * INV_SCALE + b0, v1 = acc[t][j][1] * INV_SCALE + b1;
            float v2 = acc[t][j][2] * INV_SCALE + b0, v3 = acc[t][j][3] * INV_SCALE + b1;
            if (doRelu) {
                v0 = fmaxf(v0, 0.f); v1 = fmaxf(v1, 0.f);
                v2 = fmaxf(v2, 0.f); v3 = fmaxf(v3, 0.f);
            }
            *(__half2*)&C[(size_t)r0 * EMB + col]       = __floats2half2_rn(v0, v1);
            *(__half2*)&C[(size_t)(r0 + 8) * EMB + col] = __floats2half2_rn(v2, v3);
        }
    }
}

// ---------------- FP16 HMMA GEMM 128x128 tile (O-projection), fp32 out ------
__global__ __launch_bounds__(128, 2) void tcgemm_kernel(
    const __half* __restrict__ A, const __half* __restrict__ B,
    const float* __restrict__ bias, float* __restrict__ C)
{
    constexpr int NST = 3;
    constexpr uint32_t STAGE_BYTES = 2 * TILE_B;

    extern __shared__ __align__(1024) char smem[];
    uint32_t sb = smem_to_u32(smem);
    int tid  = threadIdx.x;
    int lane = tid & 31, wid = tid >> 5;
    int nt = blockIdx.x, mt = blockIdx.y;
    int wm = wid & 1;
    int wn = wid >> 1;

    uint32_t mb_full  = sb + SMEM_DATA;
    uint32_t mb_empty = sb + SMEM_DATA + 48;

    if (tid == 0) {
        #pragma unroll
        for (int s = 0; s < NST; s++) {
            MBARRIER_INIT(mb_full + 8 * s, 1);
            MBARRIER_INIT(mb_empty + 8 * s, 128);
        }
        asm volatile("fence.proxy.async.shared::cta;" ::: "memory");
    }
    __syncthreads();

    const __half* gA = A + (size_t)mt * KCH * TILE_PAD;
    const __half* gB = B + (size_t)nt * KCH * TILE_PAD;

    int emptyPh[NST], fullPh[NST];
    #pragma unroll
    for (int s = 0; s < NST; s++) { emptyPh[s] = 1; fullPh[s] = 0; }

    auto produce = [&](int c) {
        if (tid == 0) {
            int s = c % NST;
            MBARRIER_WAIT_PARITY(mb_empty + 8 * s, emptyPh[s]);
            emptyPh[s] ^= 1;
            uint32_t dst = sb + s * STAGE_BYTES;
            uint32_t mbar = mb_full + 8 * s;
            MBARRIER_EXPECT_TX(mbar, STAGE_BYTES);
            bulk_g2s(dst,          gA + (size_t)c * TILE_PAD, TILE_B, mbar);
            bulk_g2s(dst + TILE_B, gB + (size_t)c * TILE_PAD, TILE_B, mbar);
        }
    };

    float acc[4][8][4];
    #pragma unroll
    for (int t = 0; t < 4; t++)
        #pragma unroll
        for (int j = 0; j < 8; j++)
            #pragma unroll
            for (int i = 0; i < 4; i++) acc[t][j][i] = 0.f;

    int a_mr = lane & 15;
    int a_ks = lane >> 4;
    int b_nr = ((lane >> 4) << 3) | (lane & 7);
    int b_ks = (lane >> 3) & 1;

    #pragma unroll
    for (int s = 0; s < NST; s++) produce(s);

    for (int c = 0; c < KCH; c++) {
        int s = c % NST;
        MBARRIER_WAIT_PARITY(mb_full + 8 * s, fullPh[s]);
        fullPh[s] ^= 1;

        uint32_t stB = sb + s * STAGE_BYTES;
        uint32_t aRow0 = (uint32_t)(wm * 64);

        #pragma unroll
        for (int ks = 0; ks < 4; ks++) {
            uint32_t ah[4][4], bb[4][4];
            #pragma unroll
            for (int t = 0; t < 4; t++) {
                uint32_t off = (aRow0 + t * 16 + a_mr) * 144u + ks * 32u + a_ks * 16u;
                ldsm4(ah[t], stB + off);
            }
            #pragma unroll
            for (int g = 0; g < 4; g++) {
                uint32_t off = (uint32_t)(wn * 64 + g * 16 + b_nr) * 144u + ks * 32u + b_ks * 16u;
                ldsm4(bb[g], stB + TILE_B + off);
            }
            #pragma unroll
            for (int t = 0; t < 4; t++)
                #pragma unroll
                for (int j = 0; j < 8; j++)
                    mma16816(acc[t][j], ah[t], bb[j >> 1][2 * (j & 1)], bb[j >> 1][2 * (j & 1) + 1]);
        }
        MBARRIER_ARRIVE(mb_empty + 8 * s);
        if (c + NST < KCH) produce(c + NST);
    }

    int g = lane >> 2, tq = lane & 3;
    int mbase = mt * 128 + wm * 64;
    #pragma unroll
    for (int t = 0; t < 4; t++) {
        int r0 = mbase + t * 16 + g;
        #pragma unroll
        for (int j = 0; j < 8; j++) {
            int col = nt * 128 + wn * 64 + j * 8 + tq * 2;
            float b0 = __ldg(&bias[col]), b1 = __ldg(&bias[col + 1]);
            *(float2*)&C[(size_t)r0 * EMB + col]       = make_float2(acc[t][j][0] + b0, acc[t][j][1] + b1);
            *(float2*)&C[(size_t)(r0 + 8) * EMB + col] = make_float2(acc[t][j][2] + b0, acc[t][j][3] + b1);
        }
    }
}

// ---------------- attention stage 1: HMMA kv reduction ----------------------
#define KV_LST 64
__global__ __launch_bounds__(128) void attn_kv_kernel() {
    __shared__ __half sk[KV_LST][136];
    __shared__ __half sv[KV_LST][72];
    __shared__ float ssin[KV_LST], scos[KV_LST];
    int n = blockIdx.x, seg = blockIdx.y;
    int b = n / NHEAD, hh = n % NHEAD;
    int tid = threadIdx.x, lane = tid & 31, wid = tid >> 5;
    uint32_t skb = smem_to_u32(sk), svb = smem_to_u32(sv);

    float acc[2][8][4];
    #pragma unroll
    for (int t = 0; t < 2; t++)
        #pragma unroll
        for (int j = 0; j < 8; j++)
            #pragma unroll
            for (int i = 0; i < 4; i++) acc[t][j][i] = 0.f;
    float ksum = 0.f;

    int a_sr = (lane & 7) + ((lane >> 4) << 3);
    int a_sc = ((lane >> 3) & 1) * 8;
    int b_sr = (lane & 7) + (((lane >> 3) & 1) << 3);
    int b_sc = (lane >> 4) * 8;

    int lbeg = seg * LSEG;
    for (int ls = 0; ls < LSEG; ls += KV_LST) {
        __syncthreads();
        if (tid < KV_LST) {
            int l = lbeg + ls + tid;
            float s, c;
            sincosf(0.5f * CUDART_PI_F * (float)(l + 1) / (float)LSEQ, &s, &c);
            ssin[tid] = s; scos[tid] = c;
        }
        __syncthreads();
        #pragma unroll
        for (int i = 0; i < 16; i++) {
            int idx = tid + i * 128;
            int lc = idx >> 5, g = idx & 31;
            int l = lbeg + ls + lc;
            size_t base = ((size_t)(l * BATCH + b)) * EMB + hh * HDIM + g * 2;
            __half2 kh = *(const __half2*)&d_Kh[base];
            __half2 vh = *(const __half2*)&d_Vh[base];
            float2 kf = __half22float2(kh);
            float s = ssin[lc], c = scos[lc];
            *(__half2*)&sk[lc][g * 2]      = __floats2half2_rn(kf.x * s, kf.y * s);
            *(__half2*)&sk[lc][64 + g * 2] = __floats2half2_rn(kf.x * c, kf.y * c);
            *(__half2*)&sv[lc][g * 2]      = vh;
        }
        __syncthreads();
        #pragma unroll 8
        for (int lc = 0; lc < KV_LST; lc++) ksum += __half2float(sk[lc][tid]);

        #pragma unroll
        for (int lc16 = 0; lc16 < 4; lc16++) {
            uint32_t a[2][4], bb[4][4];
            int srA = lc16 * 16 + a_sr;
            #pragma unroll
            for (int t = 0; t < 2; t++)
                ldsm4t(a[t], skb + (uint32_t)srA * 272u + (uint32_t)(wid * 32 + t * 16 + a_sc) * 2u);
            int srB = lc16 * 16 + b_sr;
            #pragma unroll
            for (int g = 0; g < 4; g++)
                ldsm4t(bb[g], svb + (uint32_t)srB * 144u + (uint32_t)(g * 16 + b_sc) * 2u);
            #pragma unroll
            for (int t = 0; t < 2; t++)
                #pragma unroll
                for (int j = 0; j < 8; j++)
                    mma16816(acc[t][j], a[t], bb[j >> 1][2 * (j & 1)], bb[j >> 1][2 * (j & 1) + 1]);
        }
    }

    float* kvp = d_kvT + ((size_t)(seg * NHEADS_TOT + n)) * 64 * 128;
    #pragma unroll
    for (int t = 0; t < 2; t++)
        #pragma unroll
        for (int j = 0; j < 8; j++) {
            int m0 = wid * 32 + t * 16 + (lane >> 2);
            int n0 = j * 8 + (lane & 3) * 2;
            kvp[n0 * 128 + m0]             = acc[t][j][0];
            kvp[(n0 + 1) * 128 + m0]       = acc[t][j][1];
            kvp[n0 * 128 + m0 + 8]         = acc[t][j][2];
            kvp[(n0 + 1) * 128 + m0 + 8]   = acc[t][j][3];
        }
    d_ksum[(seg * NHEADS_TOT + n) * 128 + tid] = ksum;
}

// ---------------- kv partial reduction: fp32 x NSEG -> fp16 -----------------
__global__ __launch_bounds__(256) void kvreduce_kernel() {
    int n = blockIdx.x;
    int tid = threadIdx.x;
    const float* kv0 = d_kvT + (size_t)n * 8192;
    #pragma unroll
    for (int i = 0; i < 32; i++) {
        int idx = tid + i * 256;
        float v = 0.f;
        #pragma unroll
        for (int s = 0; s < NSEG; s++)
            v += kv0[(size_t)s * NHEADS_TOT * 8192 + idx];
        d_kvTh[(size_t)n * 8192 + idx] = __float2half(v);
    }
    if (tid < 128) {
        float v = 0.f;
        #pragma unroll
        for (int s = 0; s < NSEG; s++)
            v += d_ksum[(s * NHEADS_TOT + n) * 128 + tid];
        d_ksumR[n * 128 + tid] = v;
    }
}

// ---------------- attention stage 2: HMMA out + z + residual ---------------
__global__ __launch_bounds__(128) void attn_out_kernel() {
    __shared__ __half skvT[64][136];
    __shared__ __half sq[128][136];
    __shared__ float sks[128];
    __shared__ float ssin[128], scos[128], sz[128];
    int n = blockIdx.x, lb = blockIdx.y;
    int b = n / NHEAD, hh = n % NHEAD;
    int tid = threadIdx.x, lane = tid & 31, wid = tid >> 5;
    int l0 = lb * 128;
    uint32_t sqb = smem_to_u32(sq), skvb = smem_to_u32(skvT);

    {
        const uint4* kvh = (const uint4*)(d_kvTh + (size_t)n * 8192);
        #pragma unroll
        for (int i = 0; i < 8; i++) {
            int idx4 = tid + i * 128;
            int row = idx4 >> 4, col = (idx4 & 15) * 8;
            *(uint4*)&skvT[row][col] = kvh[idx4];
        }
        sks[tid] = d_ksumR[n * 128 + tid];
    }
    {
        int l = l0 + tid;
        float s, c;
        sincosf(0.5f * CUDART_PI_F * (float)(l + 1) / (float)LSEQ, &s, &c);
        ssin[tid] = s; scos[tid] = c;
    }
    __syncthreads();

    #pragma unroll
    for (int i = 0; i < 32; i++) {
        int idx = tid + i * 128;
        int lc = idx >> 5, g = idx & 31;
        int m = (l0 + lc) * BATCH + b;
        __half2 qh = *(const __half2*)&d_Qh[(size_t)m * EMB + hh * HDIM + g * 2];
        float2 qf = __half22float2(qh);
        float s = ssin[lc], c = scos[lc];
        *(__half2*)&sq[lc][g * 2]      = __floats2half2_rn(qf.x * s, qf.y * s);
        *(__half2*)&sq[lc][64 + g * 2] = __floats2half2_rn(qf.x * c, qf.y * c);
    }
    __syncthreads();

    {
        float dp = 0.f;
        #pragma unroll 16
        for (int d = 0; d < 128; d++)
            dp += __half2float(sq[tid][d]) * sks[d];
        sz[tid] = 1.0f / fmaxf(dp, 1e-6f);
    }
    __syncthreads();

    float acc[2][8][4];
    #pragma unroll
    for (int t = 0; t < 2; t++)
        #pragma unroll
        for (int j = 0; j < 8; j++)
            #pragma unroll
            for (int i = 0; i < 4; i++) acc[t][j][i] = 0.f;

    int a_mr = lane & 15;
    int a_ks = lane >> 4;
    int b_nr = ((lane >> 4) << 3) | (lane & 7);
    int b_ks = (lane >> 3) & 1;

    #pragma unroll
    for (int kc = 0; kc < 8; kc++) {
        uint32_t ah[2][4], bb[4][4];
        #pragma unroll
        for (int t = 0; t < 2; t++)
            ldsm4(ah[t], sqb + (uint32_t)(wid * 32 + t * 16 + a_mr) * 272u + kc * 32u + a_ks * 16u);
        #pragma unroll
        for (int g = 0; g < 4; g++)
            ldsm4(bb[g], skvb + (uint32_t)(g * 16 + b_nr) * 272u + kc * 32u + b_ks * 16u);
        #pragma unroll
        for (int t = 0; t < 2; t++)
            #pragma unroll
            for (int j = 0; j < 8; j++)
                mma16816(acc[t][j], ah[t], bb[j >> 1][2 * (j & 1)], bb[j >> 1][2 * (j & 1) + 1]);
    }

    int g4 = lane >> 2, tq = lane & 3;
    #pragma unroll
    for (int t = 0; t < 2; t++) {
        #pragma unroll
        for (int j = 0; j < 8; j++) {
            int lloc = wid * 32 + t * 16 + g4;
            int dv = j * 8 + tq * 2;
            #pragma unroll
            for (int half = 0; half < 2; half++) {
                int ll = lloc + half * 8;
                float z = sz[ll];
                int m = (l0 + ll) * BATCH + b;
                int tile = (m >> 7) * KCH + hh;
                uint32_t ti = tiled_idx(tile, m & 127, dv);
                float2 xv = __half22float2(*(const __half2*)&d_Xh[ti]);
                float y0 = xv.x + z * acc[t][j][half * 2];
                float y1 = xv.y + z * acc[t][j][half * 2 + 1];
                *(__half2*)&d_Yh[ti] = __floats2half2_rn(y0, y1);
            }
        }
    }
}

// ---------------- launch ----------------
extern "C" void kernel_launch(void* const* d_in, const int* in_sizes, int n_in,
                              void* d_out, int out_size) {
    const float* query = (const float*)d_in[0];
    const float* Wq = (const float*)d_in[1];
    const float* bq = (const float*)d_in[2];
    const float* Wk = (const float*)d_in[3];
    const float* bk = (const float*)d_in[4];
    const float* Wv = (const float*)d_in[5];
    const float* bv = (const float*)d_in[6];
    const float* Wo = (const float*)d_in[7];
    const float* bo = (const float*)d_in[8];
    float* out = (float*)d_out;

    __half *pQh, *pKh, *pVh, *pYh, *pWo;
    unsigned char *pX8, *pWqkv8;
    cudaGetSymbolAddress((void**)&pQh, d_Qh);
    cudaGetSymbolAddress((void**)&pKh, d_Kh);
    cudaGetSymbolAddress((void**)&pVh, d_Vh);
    cudaGetSymbolAddress((void**)&pX8, d_X8);
    cudaGetSymbolAddress((void**)&pYh, d_Yh);
    cudaGetSymbolAddress((void**)&pWqkv8, d_Wqkv8);
    cudaGetSymbolAddress((void**)&pWo, d_Wo);

    cudaFuncSetAttribute(tcgemm8_kernel, cudaFuncAttributeMaxDynamicSharedMemorySize, GEMM_SMEM);
    cudaFuncSetAttribute(tcgemm_kernel,  cudaFuncAttributeMaxDynamicSharedMemorySize, GEMM_SMEM);

    dim3 tgrid(LSEQ / 32, EMB / 32, BATCH);
    transpose_kernel<<<tgrid, dim3(32, 8)>>>(query);                     // 1
    const int wgrid = (EMB * EMB + 255) / 256;
    wconv_kernel<<<dim3(wgrid, 4), 256>>>(Wq, Wk, Wv, Wo);               // 2

    // 3: combined QKV GEMM (fp8 e4m3)
    tcgemm8_kernel<<<dim3(18, MT), 128, GEMM_SMEM>>>(
        pX8, pWqkv8, bq, bk, bv, pQh, pKh, pVh, 0b011);

    // 4 (ncu capture slot): HMMA kv reduction
    attn_kv_kernel<<<dim3(NHEADS_TOT, NSEG), 128>>>();

    kvreduce_kernel<<<NHEADS_TOT, 256>>>();                              // 5

    // 6: HMMA out + z + residual
    attn_out_kernel<<<dim3(NHEADS_TOT, LSEQ / 128), 128>>>();

    // 7: O projection (fp16, fp32 out)
    tcgemm_kernel<<<dim3(6, MT), 128, GEMM_SMEM>>>(pYh, pWo, bo, out);
}

// round 15
// speedup vs baseline: 1.1284x; 1.1284x over previous
#include <cuda_runtime.h>
#include <cuda_fp16.h>
#include <math_constants.h>
#include <cstdint>

// ---------------- problem constants ----------------
#define BATCH   8
#define EMB     768
#define LSEQ    2304
#define NHEAD   12
#define HDIM    64
#define MROWS   (LSEQ*BATCH)          // 18432
#define NHEADS_TOT (BATCH*NHEAD)      // 96
#define KCH     12                    // K chunks of 64
#define MT      (MROWS/128)           // 144 GEMM M-tiles
#define NSEG    4
#define LSEG    (LSEQ/NSEG)           // 576

// padded tile: 128 rows x 72 fp16 (144B pitch) = 18432 B
#define TILE_PAD    9216
#define TILE_B      18432
#define SMEM_DATA   110592            // 3 stages x 2 tiles
#define GEMM_SMEM   (SMEM_DATA + 128)

typedef unsigned long long u64t;

// ---------------- PTX helpers ----------------
__device__ __forceinline__ uint32_t smem_to_u32(const void* p) {
    uint32_t a;
    asm("{ .reg .u64 t; cvta.to.shared.u64 t, %1; cvt.u32.u64 %0, t; }" : "=r"(a) : "l"(p));
    return a;
}
__device__ __forceinline__ void ldsm4(uint32_t* r, uint32_t addr) {
    asm volatile("ldmatrix.sync.aligned.m8n8.x4.shared.b16 {%0,%1,%2,%3}, [%4];"
        : "=r"(r[0]), "=r"(r[1]), "=r"(r[2]), "=r"(r[3]) : "r"(addr));
}
__device__ __forceinline__ void ldsm4t(uint32_t* r, uint32_t addr) {
    asm volatile("ldmatrix.sync.aligned.m8n8.x4.trans.shared.b16 {%0,%1,%2,%3}, [%4];"
        : "=r"(r[0]), "=r"(r[1]), "=r"(r[2]), "=r"(r[3]) : "r"(addr));
}
__device__ __forceinline__ void mma16816(float* c, const uint32_t* a, uint32_t b0, uint32_t b1) {
    asm volatile("mma.sync.aligned.m16n8k16.row.col.f32.f16.f16.f32 "
        "{%0,%1,%2,%3}, {%4,%5,%6,%7}, {%8,%9}, {%0,%1,%2,%3};"
        : "+f"(c[0]), "+f"(c[1]), "+f"(c[2]), "+f"(c[3])
        : "r"(a[0]), "r"(a[1]), "r"(a[2]), "r"(a[3]), "r"(b0), "r"(b1));
}
#define MBARRIER_INIT(addr, cnt) \
    asm volatile("mbarrier.init.shared.b64 [%0], %1;" :: "r"((uint32_t)(addr)), "r"((uint32_t)(cnt)) : "memory")
#define MBARRIER_ARRIVE(addr) \
    asm volatile("mbarrier.arrive.shared.b64 _, [%0];" :: "r"((uint32_t)(addr)) : "memory")
#define MBARRIER_EXPECT_TX(addr, bytes) \
    asm volatile("mbarrier.arrive.expect_tx.shared.b64 _, [%0], %1;" :: "r"((uint32_t)(addr)), "r"((uint32_t)(bytes)) : "memory")
#define MBARRIER_WAIT_PARITY(mbar_smem_addr, phase_parity) do { \
    uint32_t _mbar = (uint32_t)(mbar_smem_addr); \
    uint32_t _parity = (uint32_t)(phase_parity); \
    uint32_t _done; \
    asm volatile("{\n\t.reg .pred p;\n\t" \
        "mbarrier.try_wait.parity.acquire.cta.shared::cta.b64 p, [%1], %2;\n\t" \
        "selp.b32 %0, 1, 0, p;\n\t}" \
        : "=r"(_done) : "r"(_mbar), "r"(_parity) : "memory"); \
    if (!_done) { \
        asm volatile("{\n\t.reg .pred P1;\n\t" \
            "WAIT_LOOP_%=:\n\t" \
            "mbarrier.try_wait.parity.acquire.cta.shared::cta.b64 P1, [%0], %1, 0x989680;\n\t" \
            "@P1 bra.uni WAIT_DONE_%=;\n\t" \
            "bra.uni WAIT_LOOP_%=;\n\t" \
            "WAIT_DONE_%=:\n\t}" \
            :: "r"(_mbar), "r"(_parity) : "memory"); \
    } \
} while(0)
__device__ __forceinline__ void bulk_g2s(uint32_t dst_smem, const void* gsrc, uint32_t bytes, uint32_t mbar) {
    asm volatile(
        "cp.async.bulk.shared::cluster.global.mbarrier::complete_tx::bytes [%0], [%1], %2, [%3];"
        :: "r"(dst_smem), "l"(gsrc), "r"(bytes), "r"(mbar) : "memory");
}

// ---------------- scratch globals ----------------
__device__ __align__(1024) __half d_Qh[MROWS*EMB];
__device__ __align__(1024) __half d_Kh[MROWS*EMB];
__device__ __align__(1024) __half d_Vh[MROWS*EMB];
__device__ __align__(1024) __half d_Xh[MT*KCH*TILE_PAD];
__device__ __align__(1024) __half d_Yh[MT*KCH*TILE_PAD];
__device__ __align__(1024) __half d_Wqkv[18*KCH*TILE_PAD];
__device__ __align__(1024) __half d_Wo[6*KCH*TILE_PAD];
__device__ float d_kvT[NSEG*NHEADS_TOT*64*128];   // [seg][head][dv][dk] fp32 partials
__device__ float d_ksum[NSEG*NHEADS_TOT*128];
__device__ __align__(16) __half d_kvTh[NHEADS_TOT*64*128];  // reduced fp16 [head][dv][dk]
__device__ float d_ksumR[NHEADS_TOT*128];

__device__ __forceinline__ uint32_t tiled_idx(int tile, int r, int k) {
    return (uint32_t)tile * TILE_PAD + (uint32_t)r * 72u + (uint32_t)k;
}

// ---------------- weight conversion (all 4 weights) ----------------
__global__ void wconv_kernel(const float* __restrict__ Wq, const float* __restrict__ Wk,
                             const float* __restrict__ Wv, const float* __restrict__ Wo) {
    int which = blockIdx.y;
    const float* W = (which == 0) ? Wq : (which == 1) ? Wk : (which == 2) ? Wv : Wo;
    int idx = blockIdx.x * 256 + threadIdx.x;
    if (idx >= EMB * EMB) return;
    int n = idx / EMB, e = idx % EMB;
    __half h = __float2half(W[idx]);
    if (which < 3) {
        uint32_t t = tiled_idx((which * 6 + (n >> 7)) * KCH + (e >> 6), n & 127, e & 63);
        d_Wqkv[t] = h;
    } else {
        uint32_t t = tiled_idx(((n >> 7)) * KCH + (e >> 6), n & 127, e & 63);
        d_Wo[t] = h;
    }
}

// ---------------- transpose (B,E,L)->(L*B,E): fp16 tiled only ---------------
__global__ void transpose_kernel(const float* __restrict__ q) {
    __shared__ float tile[32][33];
    int b  = blockIdx.z;
    int l0 = blockIdx.x * 32;
    int e0 = blockIdx.y * 32;
    int tx = threadIdx.x, ty = threadIdx.y;   // 32 x 8
    const float* src = q + (size_t)b * EMB * LSEQ;
    #pragma unroll
    for (int i = 0; i < 32; i += 8)
        tile[ty + i][tx] = src[(size_t)(e0 + ty + i) * LSEQ + l0 + tx];
    __syncthreads();
    #pragma unroll
    for (int i = 0; i < 32; i += 8) {
        int l = l0 + ty + i;
        int e = e0 + tx;
        int m = l * BATCH + b;
        uint32_t t = tiled_idx((m >> 7) * KCH + (e >> 6), m & 127, e & 63);
        d_Xh[t] = __float2half(tile[tx][ty + i]);
    }
}

// ---------------- HMMA GEMM 128x128 tile, 128 threads, single product -------
// OUT32=0: fp16 output (QKV).  OUT32=1: fp32 output (O-projection).
template <int OUT32>
__global__ __launch_bounds__(128, 2) void tcgemm_kernel(
    const __half* __restrict__ A, const __half* __restrict__ B,
    const float* __restrict__ b0p, const float* __restrict__ b1p, const float* __restrict__ b2p,
    void* __restrict__ C0, void* __restrict__ C1, void* __restrict__ C2,
    int reluMask)
{
    constexpr int NST = 3;
    constexpr uint32_t STAGE_BYTES = 2 * TILE_B;

    extern __shared__ __align__(1024) char smem[];
    uint32_t sb = smem_to_u32(smem);
    int tid  = threadIdx.x;
    int lane = tid & 31, wid = tid >> 5;   // 4 warps
    int nt = blockIdx.x, mt = blockIdx.y;
    int sel = nt / 6, ntc = nt % 6;
    const float* bias = (sel == 0) ? b0p : (sel == 1) ? b1p : b2p;
    void* C = (sel == 0) ? C0 : (sel == 1) ? C1 : C2;
    int doRelu = (reluMask >> sel) & 1;
    int wm = wid & 1;      // M offset wm*64
    int wn = wid >> 1;     // N offset wn*64

    uint32_t mb_full  = sb + SMEM_DATA;
    uint32_t mb_empty = sb + SMEM_DATA + 48;

    if (tid == 0) {
        #pragma unroll
        for (int s = 0; s < NST; s++) {
            MBARRIER_INIT(mb_full + 8 * s, 1);
            MBARRIER_INIT(mb_empty + 8 * s, 128);
        }
        asm volatile("fence.proxy.async.shared::cta;" ::: "memory");
    }
    __syncthreads();

    const __half* gA = A + (size_t)mt * KCH * TILE_PAD;
    const __half* gB = B + (size_t)nt * KCH * TILE_PAD;

    int emptyPh[NST], fullPh[NST];
    #pragma unroll
    for (int s = 0; s < NST; s++) { emptyPh[s] = 1; fullPh[s] = 0; }

    auto produce = [&](int c) {
        if (tid == 0) {
            int s = c % NST;
            MBARRIER_WAIT_PARITY(mb_empty + 8 * s, emptyPh[s]);
            emptyPh[s] ^= 1;
            uint32_t dst = sb + s * STAGE_BYTES;
            uint32_t mbar = mb_full + 8 * s;
            MBARRIER_EXPECT_TX(mbar, STAGE_BYTES);
            bulk_g2s(dst,          gA + (size_t)c * TILE_PAD, TILE_B, mbar);
            bulk_g2s(dst + TILE_B, gB + (size_t)c * TILE_PAD, TILE_B, mbar);
        }
    };

    float acc[4][8][4];
    #pragma unroll
    for (int t = 0; t < 4; t++)
        #pragma unroll
        for (int j = 0; j < 8; j++)
            #pragma unroll
            for (int i = 0; i < 4; i++) acc[t][j][i] = 0.f;

    int a_mr = lane & 15;
    int a_ks = lane >> 4;
    int b_nr = ((lane >> 4) << 3) | (lane & 7);
    int b_ks = (lane >> 3) & 1;

    #pragma unroll
    for (int s = 0; s < NST; s++) produce(s);

    for (int c = 0; c < KCH; c++) {
        int s = c % NST;
        MBARRIER_WAIT_PARITY(mb_full + 8 * s, fullPh[s]);
        fullPh[s] ^= 1;

        uint32_t stB = sb + s * STAGE_BYTES;
        uint32_t aRow0 = (uint32_t)(wm * 64);

        #pragma unroll
        for (int ks = 0; ks < 4; ks++) {
            uint32_t ah[4][4], bb[4][4];
            #pragma unroll
            for (int t = 0; t < 4; t++) {
                uint32_t off = (aRow0 + t * 16 + a_mr) * 144u + ks * 32u + a_ks * 16u;
                ldsm4(ah[t], stB + off);
            }
            #pragma unroll
            for (int g = 0; g < 4; g++) {
                uint32_t off = (uint32_t)(wn * 64 + g * 16 + b_nr) * 144u + ks * 32u + b_ks * 16u;
                ldsm4(bb[g], stB + TILE_B + off);
            }
            #pragma unroll
            for (int t = 0; t < 4; t++)
                #pragma unroll
                for (int j = 0; j < 8; j++)
                    mma16816(acc[t][j], ah[t], bb[j >> 1][2 * (j & 1)], bb[j >> 1][2 * (j & 1) + 1]);
        }
        MBARRIER_ARRIVE(mb_empty + 8 * s);
        if (c + NST < KCH) produce(c + NST);
    }

    // epilogue
    int g = lane >> 2, tq = lane & 3;
    int mbase = mt * 128 + wm * 64;
    #pragma unroll
    for (int t = 0; t < 4; t++) {
        int r0 = mbase + t * 16 + g;
        #pragma unroll
        for (int j = 0; j < 8; j++) {
            int col = ntc * 128 + wn * 64 + j * 8 + tq * 2;
            float b0 = __ldg(&bias[col]), b1 = __ldg(&bias[col + 1]);
            float v0 = acc[t][j][0] + b0, v1 = acc[t][j][1] + b1;
            float v2 = acc[t][j][2] + b0, v3 = acc[t][j][3] + b1;
            if (doRelu) {
                v0 = fmaxf(v0, 0.f); v1 = fmaxf(v1, 0.f);
                v2 = fmaxf(v2, 0.f); v3 = fmaxf(v3, 0.f);
            }
            if (!OUT32) {
                __half* Ch = (__half*)C;
                *(__half2*)&Ch[(size_t)r0 * EMB + col]       = __floats2half2_rn(v0, v1);
                *(__half2*)&Ch[(size_t)(r0 + 8) * EMB + col] = __floats2half2_rn(v2, v3);
            } else {
                float* Cf = (float*)C;
                *(float2*)&Cf[(size_t)r0 * EMB + col]       = make_float2(v0, v1);
                *(float2*)&Cf[(size_t)(r0 + 8) * EMB + col] = make_float2(v2, v3);
            }
        }
    }
}

// ---------------- attention stage 1: HMMA kv reduction ----------------------
#define KV_LST 64
__global__ __launch_bounds__(128) void attn_kv_kernel() {
    __shared__ __half sk[KV_LST][136];   // k_ = [k*sin | k*cos]
    __shared__ __half sv[KV_LST][72];    // v
    __shared__ float ssin[KV_LST], scos[KV_LST];
    int n = blockIdx.x, seg = blockIdx.y;
    int b = n / NHEAD, hh = n % NHEAD;
    int tid = threadIdx.x, lane = tid & 31, wid = tid >> 5;
    uint32_t skb = smem_to_u32(sk), svb = smem_to_u32(sv);

    float acc[2][8][4];
    #pragma unroll
    for (int t = 0; t < 2; t++)
        #pragma unroll
        for (int j = 0; j < 8; j++)
            #pragma unroll
            for (int i = 0; i < 4; i++) acc[t][j][i] = 0.f;
    float ksum = 0.f;

    int a_sr = (lane & 7) + ((lane >> 4) << 3);
    int a_sc = ((lane >> 3) & 1) * 8;
    int b_sr = (lane & 7) + (((lane >> 3) & 1) << 3);
    int b_sc = (lane >> 4) * 8;

    int lbeg = seg * LSEG;
    for (int ls = 0; ls < LSEG; ls += KV_LST) {
        __syncthreads();
        if (tid < KV_LST) {
            int l = lbeg + ls + tid;
            float s, c;
            sincosf(0.5f * CUDART_PI_F * (float)(l + 1) / (float)LSEQ, &s, &c);
            ssin[tid] = s; scos[tid] = c;
        }
        __syncthreads();
        #pragma unroll
        for (int i = 0; i < 16; i++) {
            int idx = tid + i * 128;
            int lc = idx >> 5, g = idx & 31;
            int l = lbeg + ls + lc;
            size_t base = ((size_t)(l * BATCH + b)) * EMB + hh * HDIM + g * 2;
            __half2 kh = *(const __half2*)&d_Kh[base];
            __half2 vh = *(const __half2*)&d_Vh[base];
            float2 kf = __half22float2(kh);
            float s = ssin[lc], c = scos[lc];
            *(__half2*)&sk[lc][g * 2]      = __floats2half2_rn(kf.x * s, kf.y * s);
            *(__half2*)&sk[lc][64 + g * 2] = __floats2half2_rn(kf.x * c, kf.y * c);
            *(__half2*)&sv[lc][g * 2]      = vh;
        }
        __syncthreads();
        #pragma unroll 8
        for (int lc = 0; lc < KV_LST; lc++) ksum += __half2float(sk[lc][tid]);

        #pragma unroll
        for (int lc16 = 0; lc16 < 4; lc16++) {
            uint32_t a[2][4], bb[4][4];
            int srA = lc16 * 16 + a_sr;
            #pragma unroll
            for (int t = 0; t < 2; t++)
                ldsm4t(a[t], skb + (uint32_t)srA * 272u + (uint32_t)(wid * 32 + t * 16 + a_sc) * 2u);
            int srB = lc16 * 16 + b_sr;
            #pragma unroll
            for (int g = 0; g < 4; g++)
                ldsm4t(bb[g], svb + (uint32_t)srB * 144u + (uint32_t)(g * 16 + b_sc) * 2u);
            #pragma unroll
            for (int t = 0; t < 2; t++)
                #pragma unroll
                for (int j = 0; j < 8; j++)
                    mma16816(acc[t][j], a[t], bb[j >> 1][2 * (j & 1)], bb[j >> 1][2 * (j & 1) + 1]);
        }
    }

    float* kvp = d_kvT + ((size_t)(seg * NHEADS_TOT + n)) * 64 * 128;
    #pragma unroll
    for (int t = 0; t < 2; t++)
        #pragma unroll
        for (int j = 0; j < 8; j++) {
            int m0 = wid * 32 + t * 16 + (lane >> 2);
            int n0 = j * 8 + (lane & 3) * 2;
            kvp[n0 * 128 + m0]             = acc[t][j][0];
            kvp[(n0 + 1) * 128 + m0]       = acc[t][j][1];
            kvp[n0 * 128 + m0 + 8]         = acc[t][j][2];
            kvp[(n0 + 1) * 128 + m0 + 8]   = acc[t][j][3];
        }
    d_ksum[(seg * NHEADS_TOT + n) * 128 + tid] = ksum;
}

// ---------------- kv partial reduction: fp32 x NSEG -> fp16 -----------------
__global__ __launch_bounds__(256) void kvreduce_kernel() {
    int n = blockIdx.x;
    int tid = threadIdx.x;
    const float* kv0 = d_kvT + (size_t)n * 8192;
    #pragma unroll
    for (int i = 0; i < 32; i++) {
        int idx = tid + i * 256;
        float v = 0.f;
        #pragma unroll
        for (int s = 0; s < NSEG; s++)
            v += kv0[(size_t)s * NHEADS_TOT * 8192 + idx];
        d_kvTh[(size_t)n * 8192 + idx] = __float2half(v);
    }
    if (tid < 128) {
        float v = 0.f;
        #pragma unroll
        for (int s = 0; s < NSEG; s++)
            v += d_ksum[(s * NHEADS_TOT + n) * 128 + tid];
        d_ksumR[n * 128 + tid] = v;
    }
}

// ---------------- attention stage 2: HMMA out + z + residual ---------------
__global__ __launch_bounds__(128) void attn_out_kernel() {
    __shared__ __half skvT[64][136];
    __shared__ __half sq[128][136];
    __shared__ float sks[128];
    __shared__ float ssin[128], scos[128], sz[128];
    int n = blockIdx.x, lb = blockIdx.y;
    int b = n / NHEAD, hh = n % NHEAD;
    int tid = threadIdx.x, lane = tid & 31, wid = tid >> 5;
    int l0 = lb * 128;
    uint32_t sqb = smem_to_u32(sq), skvb = smem_to_u32(skvT);

    // 1: load reduced kv (fp16, 16KB) + ksum
    {
        const uint4* kvh = (const uint4*)(d_kvTh + (size_t)n * 8192);
        #pragma unroll
        for (int i = 0; i < 8; i++) {
            int idx4 = tid + i * 128;
            int row = idx4 >> 4, col = (idx4 & 15) * 8;
            *(uint4*)&skvT[row][col] = kvh[idx4];
        }
        sks[tid] = d_ksumR[n * 128 + tid];
    }
    {
        int l = l0 + tid;
        float s, c;
        sincosf(0.5f * CUDART_PI_F * (float)(l + 1) / (float)LSEQ, &s, &c);
        ssin[tid] = s; scos[tid] = c;
    }
    __syncthreads();

    // 2: build q_ tile [128 l][128 dk] fp16
    #pragma unroll
    for (int i = 0; i < 32; i++) {
        int idx = tid + i * 128;
        int lc = idx >> 5, g = idx & 31;
        int m = (l0 + lc) * BATCH + b;
        __half2 qh = *(const __half2*)&d_Qh[(size_t)m * EMB + hh * HDIM + g * 2];
        float2 qf = __half22float2(qh);
        float s = ssin[lc], c = scos[lc];
        *(__half2*)&sq[lc][g * 2]      = __floats2half2_rn(qf.x * s, qf.y * s);
        *(__half2*)&sq[lc][64 + g * 2] = __floats2half2_rn(qf.x * c, qf.y * c);
    }
    __syncthreads();

    // 3: z per l
    {
        float dp = 0.f;
        #pragma unroll 16
        for (int d = 0; d < 128; d++)
            dp += __half2float(sq[tid][d]) * sks[d];
        sz[tid] = 1.0f / fmaxf(dp, 1e-6f);
    }
    __syncthreads();

    // 4: MMA out[128l][64dv]
    float acc[2][8][4];
    #pragma unroll
    for (int t = 0; t < 2; t++)
        #pragma unroll
        for (int j = 0; j < 8; j++)
            #pragma unroll
            for (int i = 0; i < 4; i++) acc[t][j][i] = 0.f;

    int a_mr = lane & 15;
    int a_ks = lane >> 4;
    int b_nr = ((lane >> 4) << 3) | (lane & 7);
    int b_ks = (lane >> 3) & 1;

    #pragma unroll
    for (int kc = 0; kc < 8; kc++) {
        uint32_t ah[2][4], bb[4][4];
        #pragma unroll
        for (int t = 0; t < 2; t++)
            ldsm4(ah[t], sqb + (uint32_t)(wid * 32 + t * 16 + a_mr) * 272u + kc * 32u + a_ks * 16u);
        #pragma unroll
        for (int g = 0; g < 4; g++)
            ldsm4(bb[g], skvb + (uint32_t)(g * 16 + b_nr) * 272u + kc * 32u + b_ks * 16u);
        #pragma unroll
        for (int t = 0; t < 2; t++)
            #pragma unroll
            for (int j = 0; j < 8; j++)
                mma16816(acc[t][j], ah[t], bb[j >> 1][2 * (j & 1)], bb[j >> 1][2 * (j & 1) + 1]);
    }

    // 5: epilogue: y = x + z*out (x from fp16 tiled Xh) -> tiled fp16 Y
    int g4 = lane >> 2, tq = lane & 3;
    #pragma unroll
    for (int t = 0; t < 2; t++) {
        #pragma unroll
        for (int j = 0; j < 8; j++) {
            int lloc = wid * 32 + t * 16 + g4;
            int dv = j * 8 + tq * 2;
            #pragma unroll
            for (int half = 0; half < 2; half++) {
                int ll = lloc + half * 8;
                float z = sz[ll];
                int m = (l0 + ll) * BATCH + b;
                int tile = (m >> 7) * KCH + hh;
                uint32_t ti = tiled_idx(tile, m & 127, dv);
                float2 xv = __half22float2(*(const __half2*)&d_Xh[ti]);
                float y0 = xv.x + z * acc[t][j][half * 2];
                float y1 = xv.y + z * acc[t][j][half * 2 + 1];
                *(__half2*)&d_Yh[ti] = __floats2half2_rn(y0, y1);
            }
        }
    }
}

// ---------------- launch ----------------
extern "C" void kernel_launch(void* const* d_in, const int* in_sizes, int n_in,
                              void* d_out, int out_size) {
    const float* query = (const float*)d_in[0];
    const float* Wq = (const float*)d_in[1];
    const float* bq = (const float*)d_in[2];
    const float* Wk = (const float*)d_in[3];
    const float* bk = (const float*)d_in[4];
    const float* Wv = (const float*)d_in[5];
    const float* bv = (const float*)d_in[6];
    const float* Wo = (const float*)d_in[7];
    const float* bo = (const float*)d_in[8];
    float* out = (float*)d_out;

    __half *pQh, *pKh, *pVh, *pXh, *pYh, *pWqkv, *pWo;
    cudaGetSymbolAddress((void**)&pQh, d_Qh);
    cudaGetSymbolAddress((void**)&pKh, d_Kh);
    cudaGetSymbolAddress((void**)&pVh, d_Vh);
    cudaGetSymbolAddress((void**)&pXh, d_Xh);
    cudaGetSymbolAddress((void**)&pYh, d_Yh);
    cudaGetSymbolAddress((void**)&pWqkv, d_Wqkv);
    cudaGetSymbolAddress((void**)&pWo, d_Wo);

    cudaFuncSetAttribute(tcgemm_kernel<0>, cudaFuncAttributeMaxDynamicSharedMemorySize, GEMM_SMEM);
    cudaFuncSetAttribute(tcgemm_kernel<1>, cudaFuncAttributeMaxDynamicSharedMemorySize, GEMM_SMEM);

    dim3 tgrid(LSEQ / 32, EMB / 32, BATCH);
    transpose_kernel<<<tgrid, dim3(32, 8)>>>(query);                     // 1
    const int wgrid = (EMB * EMB + 255) / 256;
    wconv_kernel<<<dim3(wgrid, 4), 256>>>(Wq, Wk, Wv, Wo);               // 2

    // 3: combined QKV GEMM (fp16 single product)
    tcgemm_kernel<0><<<dim3(18, MT), 128, GEMM_SMEM>>>(
        pXh, pWqkv, bq, bk, bv, pQh, pKh, pVh, 0b011);

    // 4 (ncu capture slot): HMMA kv reduction
    attn_kv_kernel<<<dim3(NHEADS_TOT, NSEG), 128>>>();

    kvreduce_kernel<<<NHEADS_TOT, 256>>>();                              // 5

    // 6: HMMA out + z + residual
    attn_out_kernel<<<dim3(NHEADS_TOT, LSEQ / 128), 128>>>();

    // 7: O projection (fp16 single product, fp32 out)
    tcgemm_kernel<1><<<dim3(6, MT), 128, GEMM_SMEM>>>(
        pYh, pWo, bo, bo, bo, out, out, out, 0);
}

// round 16
// speedup vs baseline: 1.1643x; 1.0317x over previous
#include <cuda_runtime.h>
#include <cuda_fp16.h>
#include <math_constants.h>
#include <cstdint>

// ---------------- problem constants ----------------
#define BATCH   8
#define EMB     768
#define LSEQ    2304
#define NHEAD   12
#define HDIM    64
#define MROWS   (LSEQ*BATCH)          // 18432
#define NHEADS_TOT (BATCH*NHEAD)      // 96
#define KCH     12                    // K chunks of 64
#define MT      (MROWS/128)           // 144 GEMM M-tiles
#define NSEG    4
#define LSEG    (LSEQ/NSEG)           // 576

// padded tile: 128 rows x 72 fp16 (144B pitch) = 18432 B
#define TILE_PAD    9216
#define TILE_B      18432
#define SMEM_DATA   110592            // 3 stages x 2 tiles
#define GEMM_SMEM   (SMEM_DATA + 128)

typedef unsigned long long u64t;

// ---------------- PTX helpers ----------------
__device__ __forceinline__ uint32_t smem_to_u32(const void* p) {
    uint32_t a;
    asm("{ .reg .u64 t; cvta.to.shared.u64 t, %1; cvt.u32.u64 %0, t; }" : "=r"(a) : "l"(p));
    return a;
}
__device__ __forceinline__ void ldsm4(uint32_t* r, uint32_t addr) {
    asm volatile("ldmatrix.sync.aligned.m8n8.x4.shared.b16 {%0,%1,%2,%3}, [%4];"
        : "=r"(r[0]), "=r"(r[1]), "=r"(r[2]), "=r"(r[3]) : "r"(addr));
}
__device__ __forceinline__ void ldsm4t(uint32_t* r, uint32_t addr) {
    asm volatile("ldmatrix.sync.aligned.m8n8.x4.trans.shared.b16 {%0,%1,%2,%3}, [%4];"
        : "=r"(r[0]), "=r"(r[1]), "=r"(r[2]), "=r"(r[3]) : "r"(addr));
}
__device__ __forceinline__ void mma16816(float* c, const uint32_t* a, uint32_t b0, uint32_t b1) {
    asm volatile("mma.sync.aligned.m16n8k16.row.col.f32.f16.f16.f32 "
        "{%0,%1,%2,%3}, {%4,%5,%6,%7}, {%8,%9}, {%0,%1,%2,%3};"
        : "+f"(c[0]), "+f"(c[1]), "+f"(c[2]), "+f"(c[3])
        : "r"(a[0]), "r"(a[1]), "r"(a[2]), "r"(a[3]), "r"(b0), "r"(b1));
}
#define MBARRIER_INIT(addr, cnt) \
    asm volatile("mbarrier.init.shared.b64 [%0], %1;" :: "r"((uint32_t)(addr)), "r"((uint32_t)(cnt)) : "memory")
#define MBARRIER_ARRIVE(addr) \
    asm volatile("mbarrier.arrive.shared.b64 _, [%0];" :: "r"((uint32_t)(addr)) : "memory")
#define MBARRIER_EXPECT_TX(addr, bytes) \
    asm volatile("mbarrier.arrive.expect_tx.shared.b64 _, [%0], %1;" :: "r"((uint32_t)(addr)), "r"((uint32_t)(bytes)) : "memory")
#define MBARRIER_WAIT_PARITY(mbar_smem_addr, phase_parity) do { \
    uint32_t _mbar = (uint32_t)(mbar_smem_addr); \
    uint32_t _parity = (uint32_t)(phase_parity); \
    uint32_t _done; \
    asm volatile("{\n\t.reg .pred p;\n\t" \
        "mbarrier.try_wait.parity.acquire.cta.shared::cta.b64 p, [%1], %2;\n\t" \
        "selp.b32 %0, 1, 0, p;\n\t}" \
        : "=r"(_done) : "r"(_mbar), "r"(_parity) : "memory"); \
    if (!_done) { \
        asm volatile("{\n\t.reg .pred P1;\n\t" \
            "WAIT_LOOP_%=:\n\t" \
            "mbarrier.try_wait.parity.acquire.cta.shared::cta.b64 P1, [%0], %1, 0x989680;\n\t" \
            "@P1 bra.uni WAIT_DONE_%=;\n\t" \
            "bra.uni WAIT_LOOP_%=;\n\t" \
            "WAIT_DONE_%=:\n\t}" \
            :: "r"(_mbar), "r"(_parity) : "memory"); \
    } \
} while(0)
__device__ __forceinline__ void bulk_g2s(uint32_t dst_smem, const void* gsrc, uint32_t bytes, uint32_t mbar) {
    asm volatile(
        "cp.async.bulk.shared::cluster.global.mbarrier::complete_tx::bytes [%0], [%1], %2, [%3];"
        :: "r"(dst_smem), "l"(gsrc), "r"(bytes), "r"(mbar) : "memory");
}

// ---------------- scratch globals ----------------
__device__ __align__(1024) __half d_Qh[MROWS*EMB];
__device__ __align__(1024) __half d_Kh[MROWS*EMB];
__device__ __align__(1024) __half d_Vh[MROWS*EMB];
__device__ __align__(1024) __half d_Xh[MT*KCH*TILE_PAD];
__device__ __align__(1024) __half d_Yh[MT*KCH*TILE_PAD];
__device__ __align__(1024) __half d_Wqkv[18*KCH*TILE_PAD];
__device__ __align__(1024) __half d_Wo[6*KCH*TILE_PAD];
__device__ float d_kvT[NSEG*NHEADS_TOT*64*128];   // [seg][head][dv][dk] fp32 partials
__device__ float d_ksum[NSEG*NHEADS_TOT*128];
__device__ __align__(16) __half d_kvTh[NHEADS_TOT*64*128];  // reduced fp16 [head][dv][dk]
__device__ float d_ksumR[NHEADS_TOT*128];

__device__ __forceinline__ uint32_t tiled_idx(int tile, int r, int k) {
    return (uint32_t)tile * TILE_PAD + (uint32_t)r * 72u + (uint32_t)k;
}

// ---------------- weight conversion (vectorized: 4 elems/thread) -----------
__global__ void wconv_kernel(const float* __restrict__ Wq, const float* __restrict__ Wk,
                             const float* __restrict__ Wv, const float* __restrict__ Wo) {
    int which = blockIdx.y;
    const float* W = (which == 0) ? Wq : (which == 1) ? Wk : (which == 2) ? Wv : Wo;
    int idx = (blockIdx.x * 256 + threadIdx.x) * 4;
    if (idx >= EMB * EMB) return;
    int n = idx / EMB, e = idx % EMB;
    float4 w = *(const float4*)&W[idx];
    __half2 h01 = __floats2half2_rn(w.x, w.y);
    __half2 h23 = __floats2half2_rn(w.z, w.w);
    uint32_t t;
    if (which < 3)
        t = tiled_idx((which * 6 + (n >> 7)) * KCH + (e >> 6), n & 127, e & 63);
    else
        t = tiled_idx(((n >> 7)) * KCH + (e >> 6), n & 127, e & 63);
    __half* dst = (which < 3) ? d_Wqkv : d_Wo;
    *(__half2*)&dst[t]     = h01;
    *(__half2*)&dst[t + 2] = h23;
}

// ---------------- transpose (B,E,L)->(L*B,E): fp16 tiled only ---------------
__global__ void transpose_kernel(const float* __restrict__ q) {
    __shared__ float tile[32][33];
    int b  = blockIdx.z;
    int l0 = blockIdx.x * 32;
    int e0 = blockIdx.y * 32;
    int tx = threadIdx.x, ty = threadIdx.y;   // 32 x 8
    const float* src = q + (size_t)b * EMB * LSEQ;
    #pragma unroll
    for (int i = 0; i < 32; i += 8)
        tile[ty + i][tx] = src[(size_t)(e0 + ty + i) * LSEQ + l0 + tx];
    __syncthreads();
    #pragma unroll
    for (int i = 0; i < 32; i += 8) {
        int l = l0 + ty + i;
        int e = e0 + tx;
        int m = l * BATCH + b;
        uint32_t t = tiled_idx((m >> 7) * KCH + (e >> 6), m & 127, e & 63);
        d_Xh[t] = __float2half(tile[tx][ty + i]);
    }
}

// ---------------- HMMA GEMM 128x128 tile, 128 threads, single product -------
// OUT32=0: fp16 output (QKV).  OUT32=1: fp32 output (O-projection).
template <int OUT32>
__global__ __launch_bounds__(128, 2) void tcgemm_kernel(
    const __half* __restrict__ A, const __half* __restrict__ B,
    const float* __restrict__ b0p, const float* __restrict__ b1p, const float* __restrict__ b2p,
    void* __restrict__ C0, void* __restrict__ C1, void* __restrict__ C2,
    int reluMask)
{
    constexpr int NST = 3;
    constexpr uint32_t STAGE_BYTES = 2 * TILE_B;

    extern __shared__ __align__(1024) char smem[];
    uint32_t sb = smem_to_u32(smem);
    int tid  = threadIdx.x;
    int lane = tid & 31, wid = tid >> 5;   // 4 warps
    int nt = blockIdx.x, mt = blockIdx.y;
    int sel = nt / 6, ntc = nt % 6;
    const float* bias = (sel == 0) ? b0p : (sel == 1) ? b1p : b2p;
    void* C = (sel == 0) ? C0 : (sel == 1) ? C1 : C2;
    int doRelu = (reluMask >> sel) & 1;
    int wm = wid & 1;      // M offset wm*64
    int wn = wid >> 1;     // N offset wn*64

    uint32_t mb_full  = sb + SMEM_DATA;
    uint32_t mb_empty = sb + SMEM_DATA + 48;

    if (tid == 0) {
        #pragma unroll
        for (int s = 0; s < NST; s++) {
            MBARRIER_INIT(mb_full + 8 * s, 1);
            MBARRIER_INIT(mb_empty + 8 * s, 128);
        }
        asm volatile("fence.proxy.async.shared::cta;" ::: "memory");
    }
    __syncthreads();

    const __half* gA = A + (size_t)mt * KCH * TILE_PAD;
    const __half* gB = B + (size_t)nt * KCH * TILE_PAD;

    int emptyPh[NST], fullPh[NST];
    #pragma unroll
    for (int s = 0; s < NST; s++) { emptyPh[s] = 1; fullPh[s] = 0; }

    auto produce = [&](int c) {
        if (tid == 0) {
            int s = c % NST;
            MBARRIER_WAIT_PARITY(mb_empty + 8 * s, emptyPh[s]);
            emptyPh[s] ^= 1;
            uint32_t dst = sb + s * STAGE_BYTES;
            uint32_t mbar = mb_full + 8 * s;
            MBARRIER_EXPECT_TX(mbar, STAGE_BYTES);
            bulk_g2s(dst,          gA + (size_t)c * TILE_PAD, TILE_B, mbar);
            bulk_g2s(dst + TILE_B, gB + (size_t)c * TILE_PAD, TILE_B, mbar);
        }
    };

    float acc[4][8][4];
    #pragma unroll
    for (int t = 0; t < 4; t++)
        #pragma unroll
        for (int j = 0; j < 8; j++)
            #pragma unroll
            for (int i = 0; i < 4; i++) acc[t][j][i] = 0.f;

    int a_mr = lane & 15;
    int a_ks = lane >> 4;
    int b_nr = ((lane >> 4) << 3) | (lane & 7);
    int b_ks = (lane >> 3) & 1;

    #pragma unroll
    for (int s = 0; s < NST; s++) produce(s);

    for (int c = 0; c < KCH; c++) {
        int s = c % NST;
        MBARRIER_WAIT_PARITY(mb_full + 8 * s, fullPh[s]);
        fullPh[s] ^= 1;

        uint32_t stB = sb + s * STAGE_BYTES;
        uint32_t aRow0 = (uint32_t)(wm * 64);

        #pragma unroll
        for (int ks = 0; ks < 4; ks++) {
            uint32_t ah[4][4], bb[4][4];
            #pragma unroll
            for (int t = 0; t < 4; t++) {
                uint32_t off = (aRow0 + t * 16 + a_mr) * 144u + ks * 32u + a_ks * 16u;
                ldsm4(ah[t], stB + off);
            }
            #pragma unroll
            for (int g = 0; g < 4; g++) {
                uint32_t off = (uint32_t)(wn * 64 + g * 16 + b_nr) * 144u + ks * 32u + b_ks * 16u;
                ldsm4(bb[g], stB + TILE_B + off);
            }
            #pragma unroll
            for (int t = 0; t < 4; t++)
                #pragma unroll
                for (int j = 0; j < 8; j++)
                    mma16816(acc[t][j], ah[t], bb[j >> 1][2 * (j & 1)], bb[j >> 1][2 * (j & 1) + 1]);
        }
        MBARRIER_ARRIVE(mb_empty + 8 * s);
        if (c + NST < KCH) produce(c + NST);
    }

    // epilogue
    int g = lane >> 2, tq = lane & 3;
    int mbase = mt * 128 + wm * 64;
    #pragma unroll
    for (int t = 0; t < 4; t++) {
        int r0 = mbase + t * 16 + g;
        #pragma unroll
        for (int j = 0; j < 8; j++) {
            int col = ntc * 128 + wn * 64 + j * 8 + tq * 2;
            float b0 = __ldg(&bias[col]), b1 = __ldg(&bias[col + 1]);
            float v0 = acc[t][j][0] + b0, v1 = acc[t][j][1] + b1;
            float v2 = acc[t][j][2] + b0, v3 = acc[t][j][3] + b1;
            if (doRelu) {
                v0 = fmaxf(v0, 0.f); v1 = fmaxf(v1, 0.f);
                v2 = fmaxf(v2, 0.f); v3 = fmaxf(v3, 0.f);
            }
            if (!OUT32) {
                __half* Ch = (__half*)C;
                *(__half2*)&Ch[(size_t)r0 * EMB + col]       = __floats2half2_rn(v0, v1);
                *(__half2*)&Ch[(size_t)(r0 + 8) * EMB + col] = __floats2half2_rn(v2, v3);
            } else {
                float* Cf = (float*)C;
                *(float2*)&Cf[(size_t)r0 * EMB + col]       = make_float2(v0, v1);
                *(float2*)&Cf[(size_t)(r0 + 8) * EMB + col] = make_float2(v2, v3);
            }
        }
    }
}

// ---------------- attention stage 1: HMMA kv reduction (overlapped) ---------
#define KV_LST 64
#define KV_NST (LSEG/KV_LST)     // 9
__global__ __launch_bounds__(128) void attn_kv_kernel() {
    __shared__ __half sk[KV_LST][136];   // k_ = [k*sin | k*cos]
    __shared__ __half sv[KV_LST][72];    // v
    __shared__ float ssin[LSEG], scos[LSEG];
    int n = blockIdx.x, seg = blockIdx.y;
    int b = n / NHEAD, hh = n % NHEAD;
    int tid = threadIdx.x, lane = tid & 31, wid = tid >> 5;
    uint32_t skb = smem_to_u32(sk), svb = smem_to_u32(sv);
    int lbeg = seg * LSEG;

    // precompute sin/cos for the whole segment once
    for (int i = tid; i < LSEG; i += 128) {
        float s, c;
        sincosf(0.5f * CUDART_PI_F * (float)(lbeg + i + 1) / (float)LSEQ, &s, &c);
        ssin[i] = s; scos[i] = c;
    }

    float acc[2][8][4];
    #pragma unroll
    for (int t = 0; t < 2; t++)
        #pragma unroll
        for (int j = 0; j < 8; j++)
            #pragma unroll
            for (int i = 0; i < 4; i++) acc[t][j][i] = 0.f;
    float ksum = 0.f;

    int a_sr = (lane & 7) + ((lane >> 4) << 3);
    int a_sc = ((lane >> 3) & 1) * 8;
    int b_sr = (lane & 7) + (((lane >> 3) & 1) << 3);
    int b_sc = (lane >> 4) * 8;

    // register staging: each thread owns 16 (lc,g) slots
    __half2 kreg[16], vreg[16];
    auto loadRegs = [&](int ls) {
        #pragma unroll
        for (int i = 0; i < 16; i++) {
            int idx = tid + i * 128;
            int lc = idx >> 5, g = idx & 31;
            size_t base = ((size_t)((lbeg + ls + lc) * BATCH + b)) * EMB + hh * HDIM + g * 2;
            kreg[i] = *(const __half2*)&d_Kh[base];
            vreg[i] = *(const __half2*)&d_Vh[base];
        }
    };

    loadRegs(0);
    __syncthreads();   // ssin/scos ready

    for (int ls = 0; ls < LSEG; ls += KV_LST) {
        // store staged registers to smem with sin/cos scaling
        #pragma unroll
        for (int i = 0; i < 16; i++) {
            int idx = tid + i * 128;
            int lc = idx >> 5, g = idx & 31;
            float2 kf = __half22float2(kreg[i]);
            float s = ssin[ls + lc], c = scos[ls + lc];
            *(__half2*)&sk[lc][g * 2]      = __floats2half2_rn(kf.x * s, kf.y * s);
            *(__half2*)&sk[lc][64 + g * 2] = __floats2half2_rn(kf.x * c, kf.y * c);
            *(__half2*)&sv[lc][g * 2]      = vreg[i];
        }
        __syncthreads();

        // prefetch next stage (global latency hidden behind ksum + MMA)
        if (ls + KV_LST < LSEG) loadRegs(ls + KV_LST);

        #pragma unroll 8
        for (int lc = 0; lc < KV_LST; lc++) ksum += __half2float(sk[lc][tid]);

        #pragma unroll
        for (int lc16 = 0; lc16 < 4; lc16++) {
            uint32_t a[2][4], bb[4][4];
            int srA = lc16 * 16 + a_sr;
            #pragma unroll
            for (int t = 0; t < 2; t++)
                ldsm4t(a[t], skb + (uint32_t)srA * 272u + (uint32_t)(wid * 32 + t * 16 + a_sc) * 2u);
            int srB = lc16 * 16 + b_sr;
            #pragma unroll
            for (int g = 0; g < 4; g++)
                ldsm4t(bb[g], svb + (uint32_t)srB * 144u + (uint32_t)(g * 16 + b_sc) * 2u);
            #pragma unroll
            for (int t = 0; t < 2; t++)
                #pragma unroll
                for (int j = 0; j < 8; j++)
                    mma16816(acc[t][j], a[t], bb[j >> 1][2 * (j & 1)], bb[j >> 1][2 * (j & 1) + 1]);
        }
        __syncthreads();
    }

    float* kvp = d_kvT + ((size_t)(seg * NHEADS_TOT + n)) * 64 * 128;
    #pragma unroll
    for (int t = 0; t < 2; t++)
        #pragma unroll
        for (int j = 0; j < 8; j++) {
            int m0 = wid * 32 + t * 16 + (lane >> 2);
            int n0 = j * 8 + (lane & 3) * 2;
            kvp[n0 * 128 + m0]             = acc[t][j][0];
            kvp[(n0 + 1) * 128 + m0]       = acc[t][j][1];
            kvp[n0 * 128 + m0 + 8]         = acc[t][j][2];
            kvp[(n0 + 1) * 128 + m0 + 8]   = acc[t][j][3];
        }
    d_ksum[(seg * NHEADS_TOT + n) * 128 + tid] = ksum;
}

// ---------------- kv partial reduction: fp32 x NSEG -> fp16 -----------------
__global__ __launch_bounds__(256) void kvreduce_kernel() {
    int n = blockIdx.x;
    int tid = threadIdx.x;
    const float* kv0 = d_kvT + (size_t)n * 8192;
    #pragma unroll
    for (int i = 0; i < 32; i++) {
        int idx = tid + i * 256;
        float v = 0.f;
        #pragma unroll
        for (int s = 0; s < NSEG; s++)
            v += kv0[(size_t)s * NHEADS_TOT * 8192 + idx];
        d_kvTh[(size_t)n * 8192 + idx] = __float2half(v);
    }
    if (tid < 128) {
        float v = 0.f;
        #pragma unroll
        for (int s = 0; s < NSEG; s++)
            v += d_ksum[(s * NHEADS_TOT + n) * 128 + tid];
        d_ksumR[n * 128 + tid] = v;
    }
}

// ---------------- attention stage 2: HMMA out + z + residual ---------------
__global__ __launch_bounds__(128) void attn_out_kernel() {
    __shared__ __half skvT[64][136];
    __shared__ __half sq[128][136];
    __shared__ float sks[128];
    __shared__ float ssin[128], scos[128], sz[128];
    int n = blockIdx.x, lb = blockIdx.y;
    int b = n / NHEAD, hh = n % NHEAD;
    int tid = threadIdx.x, lane = tid & 31, wid = tid >> 5;
    int l0 = lb * 128;
    uint32_t sqb = smem_to_u32(sq), skvb = smem_to_u32(skvT);

    // 1: load reduced kv (fp16, 16KB) + ksum
    {
        const uint4* kvh = (const uint4*)(d_kvTh + (size_t)n * 8192);
        #pragma unroll
        for (int i = 0; i < 8; i++) {
            int idx4 = tid + i * 128;
            int row = idx4 >> 4, col = (idx4 & 15) * 8;
            *(uint4*)&skvT[row][col] = kvh[idx4];
        }
        sks[tid] = d_ksumR[n * 128 + tid];
    }
    {
        int l = l0 + tid;
        float s, c;
        sincosf(0.5f * CUDART_PI_F * (float)(l + 1) / (float)LSEQ, &s, &c);
        ssin[tid] = s; scos[tid] = c;
    }
    __syncthreads();

    // 2: build q_ tile [128 l][128 dk] fp16
    #pragma unroll
    for (int i = 0; i < 32; i++) {
        int idx = tid + i * 128;
        int lc = idx >> 5, g = idx & 31;
        int m = (l0 + lc) * BATCH + b;
        __half2 qh = *(const __half2*)&d_Qh[(size_t)m * EMB + hh * HDIM + g * 2];
        float2 qf = __half22float2(qh);
        float s = ssin[lc], c = scos[lc];
        *(__half2*)&sq[lc][g * 2]      = __floats2half2_rn(qf.x * s, qf.y * s);
        *(__half2*)&sq[lc][64 + g * 2] = __floats2half2_rn(qf.x * c, qf.y * c);
    }
    __syncthreads();

    // 3: z per l
    {
        float dp = 0.f;
        #pragma unroll 16
        for (int d = 0; d < 128; d++)
            dp += __half2float(sq[tid][d]) * sks[d];
        sz[tid] = 1.0f / fmaxf(dp, 1e-6f);
    }
    __syncthreads();

    // 4: MMA out[128l][64dv]
    float acc[2][8][4];
    #pragma unroll
    for (int t = 0; t < 2; t++)
        #pragma unroll
        for (int j = 0; j < 8; j++)
            #pragma unroll
            for (int i = 0; i < 4; i++) acc[t][j][i] = 0.f;

    int a_mr = lane & 15;
    int a_ks = lane >> 4;
    int b_nr = ((lane >> 4) << 3) | (lane & 7);
    int b_ks = (lane >> 3) & 1;

    #pragma unroll
    for (int kc = 0; kc < 8; kc++) {
        uint32_t ah[2][4], bb[4][4];
        #pragma unroll
        for (int t = 0; t < 2; t++)
            ldsm4(ah[t], sqb + (uint32_t)(wid * 32 + t * 16 + a_mr) * 272u + kc * 32u + a_ks * 16u);
        #pragma unroll
        for (int g = 0; g < 4; g++)
            ldsm4(bb[g], skvb + (uint32_t)(g * 16 + b_nr) * 272u + kc * 32u + b_ks * 16u);
        #pragma unroll
        for (int t = 0; t < 2; t++)
            #pragma unroll
            for (int j = 0; j < 8; j++)
                mma16816(acc[t][j], ah[t], bb[j >> 1][2 * (j & 1)], bb[j >> 1][2 * (j & 1) + 1]);
    }

    // 5: epilogue: y = x + z*out (x from fp16 tiled Xh) -> tiled fp16 Y
    int g4 = lane >> 2, tq = lane & 3;
    #pragma unroll
    for (int t = 0; t < 2; t++) {
        #pragma unroll
        for (int j = 0; j < 8; j++) {
            int lloc = wid * 32 + t * 16 + g4;
            int dv = j * 8 + tq * 2;
            #pragma unroll
            for (int half = 0; half < 2; half++) {
                int ll = lloc + half * 8;
                float z = sz[ll];
                int m = (l0 + ll) * BATCH + b;
                int tile = (m >> 7) * KCH + hh;
                uint32_t ti = tiled_idx(tile, m & 127, dv);
                float2 xv = __half22float2(*(const __half2*)&d_Xh[ti]);
                float y0 = xv.x + z * acc[t][j][half * 2];
                float y1 = xv.y + z * acc[t][j][half * 2 + 1];
                *(__half2*)&d_Yh[ti] = __floats2half2_rn(y0, y1);
            }
        }
    }
}

// ---------------- launch ----------------
extern "C" void kernel_launch(void* const* d_in, const int* in_sizes, int n_in,
                              void* d_out, int out_size) {
    const float* query = (const float*)d_in[0];
    const float* Wq = (const float*)d_in[1];
    const float* bq = (const float*)d_in[2];
    const float* Wk = (const float*)d_in[3];
    const float* bk = (const float*)d_in[4];
    const float* Wv = (const float*)d_in[5];
    const float* bv = (const float*)d_in[6];
    const float* Wo = (const float*)d_in[7];
    const float* bo = (const float*)d_in[8];
    float* out = (float*)d_out;

    __half *pQh, *pKh, *pVh, *pXh, *pYh, *pWqkv, *pWo;
    cudaGetSymbolAddress((void**)&pQh, d_Qh);
    cudaGetSymbolAddress((void**)&pKh, d_Kh);
    cudaGetSymbolAddress((void**)&pVh, d_Vh);
    cudaGetSymbolAddress((void**)&pXh, d_Xh);
    cudaGetSymbolAddress((void**)&pYh, d_Yh);
    cudaGetSymbolAddress((void**)&pWqkv, d_Wqkv);
    cudaGetSymbolAddress((void**)&pWo, d_Wo);

    cudaFuncSetAttribute(tcgemm_kernel<0>, cudaFuncAttributeMaxDynamicSharedMemorySize, GEMM_SMEM);
    cudaFuncSetAttribute(tcgemm_kernel<1>, cudaFuncAttributeMaxDynamicSharedMemorySize, GEMM_SMEM);

    dim3 tgrid(LSEQ / 32, EMB / 32, BATCH);
    transpose_kernel<<<tgrid, dim3(32, 8)>>>(query);                     // 1
    const int wgrid = (EMB * EMB / 4 + 255) / 256;
    wconv_kernel<<<dim3(wgrid, 4), 256>>>(Wq, Wk, Wv, Wo);               // 2

    // 3: combined QKV GEMM (fp16 single product)
    tcgemm_kernel<0><<<dim3(18, MT), 128, GEMM_SMEM>>>(
        pXh, pWqkv, bq, bk, bv, pQh, pKh, pVh, 0b011);

    // 4 (ncu capture slot): HMMA kv reduction
    attn_kv_kernel<<<dim3(NHEADS_TOT, NSEG), 128>>>();

    kvreduce_kernel<<<NHEADS_TOT, 256>>>();                              // 5

    // 6: HMMA out + z + residual
    attn_out_kernel<<<dim3(NHEADS_TOT, LSEQ / 128), 128>>>();

    // 7: O projection (fp16 single product, fp32 out)
    tcgemm_kernel<1><<<dim3(6, MT), 128, GEMM_SMEM>>>(
        pYh, pWo, bo, bo, bo, out, out, out, 0);
}

// round 17
// speedup vs baseline: 1.1880x; 1.0204x over previous
#include <cuda_runtime.h>
#include <cuda_fp16.h>
#include <math_constants.h>
#include <cstdint>

// ---------------- problem constants ----------------
#define BATCH   8
#define EMB     768
#define LSEQ    2304
#define NHEAD   12
#define HDIM    64
#define MROWS   (LSEQ*BATCH)          // 18432
#define NHEADS_TOT (BATCH*NHEAD)      // 96
#define KCH     12                    // K chunks of 64
#define MT      (MROWS/128)           // 144 GEMM M-tiles
#define NSEG    4
#define LSEG    (LSEQ/NSEG)           // 576

// padded tile: 128 rows x 72 fp16 (144B pitch) = 18432 B
#define TILE_PAD    9216
#define TILE_B      18432
#define SMEM_DATA   110592            // 3 stages x 2 tiles
#define GEMM_SMEM   (SMEM_DATA + 128)

// prep kernel dispatch
#define TRANS_BLOCKS (72*24*8)        // 13824
#define WCONV_BLOCKS (576*4)          // 2304

typedef unsigned long long u64t;

// ---------------- PTX helpers ----------------
__device__ __forceinline__ uint32_t smem_to_u32(const void* p) {
    uint32_t a;
    asm("{ .reg .u64 t; cvta.to.shared.u64 t, %1; cvt.u32.u64 %0, t; }" : "=r"(a) : "l"(p));
    return a;
}
__device__ __forceinline__ void ldsm4(uint32_t* r, uint32_t addr) {
    asm volatile("ldmatrix.sync.aligned.m8n8.x4.shared.b16 {%0,%1,%2,%3}, [%4];"
        : "=r"(r[0]), "=r"(r[1]), "=r"(r[2]), "=r"(r[3]) : "r"(addr));
}
__device__ __forceinline__ void ldsm4t(uint32_t* r, uint32_t addr) {
    asm volatile("ldmatrix.sync.aligned.m8n8.x4.trans.shared.b16 {%0,%1,%2,%3}, [%4];"
        : "=r"(r[0]), "=r"(r[1]), "=r"(r[2]), "=r"(r[3]) : "r"(addr));
}
__device__ __forceinline__ void mma16816(float* c, const uint32_t* a, uint32_t b0, uint32_t b1) {
    asm volatile("mma.sync.aligned.m16n8k16.row.col.f32.f16.f16.f32 "
        "{%0,%1,%2,%3}, {%4,%5,%6,%7}, {%8,%9}, {%0,%1,%2,%3};"
        : "+f"(c[0]), "+f"(c[1]), "+f"(c[2]), "+f"(c[3])
        : "r"(a[0]), "r"(a[1]), "r"(a[2]), "r"(a[3]), "r"(b0), "r"(b1));
}
#define MBARRIER_INIT(addr, cnt) \
    asm volatile("mbarrier.init.shared.b64 [%0], %1;" :: "r"((uint32_t)(addr)), "r"((uint32_t)(cnt)) : "memory")
#define MBARRIER_ARRIVE(addr) \
    asm volatile("mbarrier.arrive.shared.b64 _, [%0];" :: "r"((uint32_t)(addr)) : "memory")
#define MBARRIER_EXPECT_TX(addr, bytes) \
    asm volatile("mbarrier.arrive.expect_tx.shared.b64 _, [%0], %1;" :: "r"((uint32_t)(addr)), "r"((uint32_t)(bytes)) : "memory")
#define MBARRIER_WAIT_PARITY(mbar_smem_addr, phase_parity) do { \
    uint32_t _mbar = (uint32_t)(mbar_smem_addr); \
    uint32_t _parity = (uint32_t)(phase_parity); \
    uint32_t _done; \
    asm volatile("{\n\t.reg .pred p;\n\t" \
        "mbarrier.try_wait.parity.acquire.cta.shared::cta.b64 p, [%1], %2;\n\t" \
        "selp.b32 %0, 1, 0, p;\n\t}" \
        : "=r"(_done) : "r"(_mbar), "r"(_parity) : "memory"); \
    if (!_done) { \
        asm volatile("{\n\t.reg .pred P1;\n\t" \
            "WAIT_LOOP_%=:\n\t" \
            "mbarrier.try_wait.parity.acquire.cta.shared::cta.b64 P1, [%0], %1, 0x989680;\n\t" \
            "@P1 bra.uni WAIT_DONE_%=;\n\t" \
            "bra.uni WAIT_LOOP_%=;\n\t" \
            "WAIT_DONE_%=:\n\t}" \
            :: "r"(_mbar), "r"(_parity) : "memory"); \
    } \
} while(0)
__device__ __forceinline__ void bulk_g2s(uint32_t dst_smem, const void* gsrc, uint32_t bytes, uint32_t mbar) {
    asm volatile(
        "cp.async.bulk.shared::cluster.global.mbarrier::complete_tx::bytes [%0], [%1], %2, [%3];"
        :: "r"(dst_smem), "l"(gsrc), "r"(bytes), "r"(mbar) : "memory");
}

// ---------------- scratch globals ----------------
__device__ __align__(1024) __half d_Qh[MROWS*EMB];
__device__ __align__(1024) __half d_Kh[MROWS*EMB];
__device__ __align__(1024) __half d_Vh[MROWS*EMB];
__device__ __align__(1024) __half d_Xh[MT*KCH*TILE_PAD];
__device__ __align__(1024) __half d_Yh[MT*KCH*TILE_PAD];
__device__ __align__(1024) __half d_Wqkv[18*KCH*TILE_PAD];
__device__ __align__(1024) __half d_Wo[6*KCH*TILE_PAD];
__device__ float d_kvT[NSEG*NHEADS_TOT*64*128];   // [seg][head][dv][dk] fp32 partials
__device__ float d_ksum[NSEG*NHEADS_TOT*128];
__device__ __align__(16) __half d_kvTh[NHEADS_TOT*64*128];  // reduced fp16 [head][dv][dk]
__device__ float d_ksumR[NHEADS_TOT*128];

__device__ __forceinline__ uint32_t tiled_idx(int tile, int r, int k) {
    return (uint32_t)tile * TILE_PAD + (uint32_t)r * 72u + (uint32_t)k;
}

// ---------------- fused prep: transpose + weight conversion ----------------
__global__ __launch_bounds__(256) void prep_kernel(
    const float* __restrict__ q,
    const float* __restrict__ Wq, const float* __restrict__ Wk,
    const float* __restrict__ Wv, const float* __restrict__ Wo) {
    __shared__ float tile[32][33];
    int bid = blockIdx.x;
    int tid = threadIdx.x;
    if (bid < TRANS_BLOCKS) {
        int b   = bid / 1728;
        int rem = bid % 1728;
        int l0 = (rem % 72) * 32;
        int e0 = (rem / 72) * 32;
        int tx = tid & 31, ty = tid >> 5;   // 32 x 8
        const float* src = q + (size_t)b * EMB * LSEQ;
        #pragma unroll
        for (int i = 0; i < 32; i += 8)
            tile[ty + i][tx] = src[(size_t)(e0 + ty + i) * LSEQ + l0 + tx];
        __syncthreads();
        #pragma unroll
        for (int i = 0; i < 32; i += 8) {
            int l = l0 + ty + i;
            int e = e0 + tx;
            int m = l * BATCH + b;
            uint32_t t = tiled_idx((m >> 7) * KCH + (e >> 6), m & 127, e & 63);
            d_Xh[t] = __float2half(tile[tx][ty + i]);
        }
    } else {
        int wb = bid - TRANS_BLOCKS;        // 0..2303
        int which = wb / 576;
        int blk   = wb % 576;
        const float* W = (which == 0) ? Wq : (which == 1) ? Wk : (which == 2) ? Wv : Wo;
        int idx = (blk * 256 + tid) * 4;
        int n = idx / EMB, e = idx % EMB;
        float4 w = *(const float4*)&W[idx];
        __half2 h01 = __floats2half2_rn(w.x, w.y);
        __half2 h23 = __floats2half2_rn(w.z, w.w);
        uint32_t t;
        if (which < 3)
            t = tiled_idx((which * 6 + (n >> 7)) * KCH + (e >> 6), n & 127, e & 63);
        else
            t = tiled_idx(((n >> 7)) * KCH + (e >> 6), n & 127, e & 63);
        __half* dst = (which < 3) ? d_Wqkv : d_Wo;
        *(__half2*)&dst[t]     = h01;
        *(__half2*)&dst[t + 2] = h23;
    }
}

// ---------------- HMMA GEMM 128x128 tile, 128 threads, single product -------
// OUT32=0: fp16 output (QKV).  OUT32=1: fp32 output (O-projection).
template <int OUT32>
__global__ __launch_bounds__(128, 2) void tcgemm_kernel(
    const __half* __restrict__ A, const __half* __restrict__ B,
    const float* __restrict__ b0p, const float* __restrict__ b1p, const float* __restrict__ b2p,
    void* __restrict__ C0, void* __restrict__ C1, void* __restrict__ C2,
    int reluMask)
{
    constexpr int NST = 3;
    constexpr uint32_t STAGE_BYTES = 2 * TILE_B;

    extern __shared__ __align__(1024) char smem[];
    uint32_t sb = smem_to_u32(smem);
    int tid  = threadIdx.x;
    int lane = tid & 31, wid = tid >> 5;   // 4 warps
    int nt = blockIdx.x, mt = blockIdx.y;
    int sel = nt / 6, ntc = nt % 6;
    const float* bias = (sel == 0) ? b0p : (sel == 1) ? b1p : b2p;
    void* C = (sel == 0) ? C0 : (sel == 1) ? C1 : C2;
    int doRelu = (reluMask >> sel) & 1;
    int wm = wid & 1;      // M offset wm*64
    int wn = wid >> 1;     // N offset wn*64

    uint32_t mb_full  = sb + SMEM_DATA;
    uint32_t mb_empty = sb + SMEM_DATA + 48;

    if (tid == 0) {
        #pragma unroll
        for (int s = 0; s < NST; s++) {
            MBARRIER_INIT(mb_full + 8 * s, 1);
            MBARRIER_INIT(mb_empty + 8 * s, 128);
        }
        asm volatile("fence.proxy.async.shared::cta;" ::: "memory");
    }
    __syncthreads();

    const __half* gA = A + (size_t)mt * KCH * TILE_PAD;
    const __half* gB = B + (size_t)nt * KCH * TILE_PAD;

    int emptyPh[NST], fullPh[NST];
    #pragma unroll
    for (int s = 0; s < NST; s++) { emptyPh[s] = 1; fullPh[s] = 0; }

    auto produce = [&](int c) {
        if (tid == 0) {
            int s = c % NST;
            MBARRIER_WAIT_PARITY(mb_empty + 8 * s, emptyPh[s]);
            emptyPh[s] ^= 1;
            uint32_t dst = sb + s * STAGE_BYTES;
            uint32_t mbar = mb_full + 8 * s;
            MBARRIER_EXPECT_TX(mbar, STAGE_BYTES);
            bulk_g2s(dst,          gA + (size_t)c * TILE_PAD, TILE_B, mbar);
            bulk_g2s(dst + TILE_B, gB + (size_t)c * TILE_PAD, TILE_B, mbar);
        }
    };

    float acc[4][8][4];
    #pragma unroll
    for (int t = 0; t < 4; t++)
        #pragma unroll
        for (int j = 0; j < 8; j++)
            #pragma unroll
            for (int i = 0; i < 4; i++) acc[t][j][i] = 0.f;

    int a_mr = lane & 15;
    int a_ks = lane >> 4;
    int b_nr = ((lane >> 4) << 3) | (lane & 7);
    int b_ks = (lane >> 3) & 1;

    #pragma unroll
    for (int s = 0; s < NST; s++) produce(s);

    for (int c = 0; c < KCH; c++) {
        int s = c % NST;
        MBARRIER_WAIT_PARITY(mb_full + 8 * s, fullPh[s]);
        fullPh[s] ^= 1;

        uint32_t stB = sb + s * STAGE_BYTES;
        uint32_t aRow0 = (uint32_t)(wm * 64);

        #pragma unroll
        for (int ks = 0; ks < 4; ks++) {
            uint32_t ah[4][4], bb[4][4];
            #pragma unroll
            for (int t = 0; t < 4; t++) {
                uint32_t off = (aRow0 + t * 16 + a_mr) * 144u + ks * 32u + a_ks * 16u;
                ldsm4(ah[t], stB + off);
            }
            #pragma unroll
            for (int g = 0; g < 4; g++) {
                uint32_t off = (uint32_t)(wn * 64 + g * 16 + b_nr) * 144u + ks * 32u + b_ks * 16u;
                ldsm4(bb[g], stB + TILE_B + off);
            }
            #pragma unroll
            for (int t = 0; t < 4; t++)
                #pragma unroll
                for (int j = 0; j < 8; j++)
                    mma16816(acc[t][j], ah[t], bb[j >> 1][2 * (j & 1)], bb[j >> 1][2 * (j & 1) + 1]);
        }
        MBARRIER_ARRIVE(mb_empty + 8 * s);
        if (c + NST < KCH) produce(c + NST);
    }

    // epilogue
    int g = lane >> 2, tq = lane & 3;
    int mbase = mt * 128 + wm * 64;
    #pragma unroll
    for (int t = 0; t < 4; t++) {
        int r0 = mbase + t * 16 + g;
        #pragma unroll
        for (int j = 0; j < 8; j++) {
            int col = ntc * 128 + wn * 64 + j * 8 + tq * 2;
            float b0 = __ldg(&bias[col]), b1 = __ldg(&bias[col + 1]);
            float v0 = acc[t][j][0] + b0, v1 = acc[t][j][1] + b1;
            float v2 = acc[t][j][2] + b0, v3 = acc[t][j][3] + b1;
            if (doRelu) {
                v0 = fmaxf(v0, 0.f); v1 = fmaxf(v1, 0.f);
                v2 = fmaxf(v2, 0.f); v3 = fmaxf(v3, 0.f);
            }
            if (!OUT32) {
                __half* Ch = (__half*)C;
                *(__half2*)&Ch[(size_t)r0 * EMB + col]       = __floats2half2_rn(v0, v1);
                *(__half2*)&Ch[(size_t)(r0 + 8) * EMB + col] = __floats2half2_rn(v2, v3);
            } else {
                float* Cf = (float*)C;
                *(float2*)&Cf[(size_t)r0 * EMB + col]       = make_float2(v0, v1);
                *(float2*)&Cf[(size_t)(r0 + 8) * EMB + col] = make_float2(v2, v3);
            }
        }
    }
}

// ---------------- attention stage 1: HMMA kv reduction (overlapped) ---------
// ksum computed via ones-operand MMA (reuses A fragments; no scalar loop).
#define KV_LST 64
__global__ __launch_bounds__(128) void attn_kv_kernel() {
    __shared__ __half sk[KV_LST][136];   // k_ = [k*sin | k*cos]
    __shared__ __half sv[KV_LST][72];    // v
    __shared__ float ssin[LSEG], scos[LSEG];
    int n = blockIdx.x, seg = blockIdx.y;
    int b = n / NHEAD, hh = n % NHEAD;
    int tid = threadIdx.x, lane = tid & 31, wid = tid >> 5;
    uint32_t skb = smem_to_u32(sk), svb = smem_to_u32(sv);
    int lbeg = seg * LSEG;
    const uint32_t ONES = 0x3C003C00u;   // half2(1.0, 1.0)

    for (int i = tid; i < LSEG; i += 128) {
        float s, c;
        sincosf(0.5f * CUDART_PI_F * (float)(lbeg + i + 1) / (float)LSEQ, &s, &c);
        ssin[i] = s; scos[i] = c;
    }

    float acc[2][8][4];
    #pragma unroll
    for (int t = 0; t < 2; t++)
        #pragma unroll
        for (int j = 0; j < 8; j++)
            #pragma unroll
            for (int i = 0; i < 4; i++) acc[t][j][i] = 0.f;
    float acc_ks[2][4];
    #pragma unroll
    for (int t = 0; t < 2; t++)
        #pragma unroll
        for (int i = 0; i < 4; i++) acc_ks[t][i] = 0.f;

    int a_sr = (lane & 7) + ((lane >> 4) << 3);
    int a_sc = ((lane >> 3) & 1) * 8;
    int b_sr = (lane & 7) + (((lane >> 3) & 1) << 3);
    int b_sc = (lane >> 4) * 8;

    __half2 kreg[16], vreg[16];
    auto loadRegs = [&](int ls) {
        #pragma unroll
        for (int i = 0; i < 16; i++) {
            int idx = tid + i * 128;
            int lc = idx >> 5, g = idx & 31;
            size_t base = ((size_t)((lbeg + ls + lc) * BATCH + b)) * EMB + hh * HDIM + g * 2;
            kreg[i] = *(const __half2*)&d_Kh[base];
            vreg[i] = *(const __half2*)&d_Vh[base];
        }
    };

    loadRegs(0);
    __syncthreads();

    for (int ls = 0; ls < LSEG; ls += KV_LST) {
        #pragma unroll
        for (int i = 0; i < 16; i++) {
            int idx = tid + i * 128;
            int lc = idx >> 5, g = idx & 31;
            __half2 sh = __half2half2(__float2half(ssin[ls + lc]));
            __half2 ch = __half2half2(__float2half(scos[ls + lc]));
            *(__half2*)&sk[lc][g * 2]      = __hmul2(kreg[i], sh);
            *(__half2*)&sk[lc][64 + g * 2] = __hmul2(kreg[i], ch);
            *(__half2*)&sv[lc][g * 2]      = vreg[i];
        }
        __syncthreads();

        if (ls + KV_LST < LSEG) loadRegs(ls + KV_LST);

        #pragma unroll
        for (int lc16 = 0; lc16 < 4; lc16++) {
            uint32_t a[2][4], bb[4][4];
            int srA = lc16 * 16 + a_sr;
            #pragma unroll
            for (int t = 0; t < 2; t++)
                ldsm4t(a[t], skb + (uint32_t)srA * 272u + (uint32_t)(wid * 32 + t * 16 + a_sc) * 2u);
            int srB = lc16 * 16 + b_sr;
            #pragma unroll
            for (int g = 0; g < 4; g++)
                ldsm4t(bb[g], svb + (uint32_t)srB * 144u + (uint32_t)(g * 16 + b_sc) * 2u);
            #pragma unroll
            for (int t = 0; t < 2; t++) {
                mma16816(acc_ks[t], a[t], ONES, ONES);   // ksum row-sums
                #pragma unroll
                for (int j = 0; j < 8; j++)
                    mma16816(acc[t][j], a[t], bb[j >> 1][2 * (j & 1)], bb[j >> 1][2 * (j & 1) + 1]);
            }
        }
        __syncthreads();
    }

    float* kvp = d_kvT + ((size_t)(seg * NHEADS_TOT + n)) * 64 * 128;
    #pragma unroll
    for (int t = 0; t < 2; t++)
        #pragma unroll
        for (int j = 0; j < 8; j++) {
            int m0 = wid * 32 + t * 16 + (lane >> 2);
            int n0 = j * 8 + (lane & 3) * 2;
            kvp[n0 * 128 + m0]             = acc[t][j][0];
            kvp[(n0 + 1) * 128 + m0]       = acc[t][j][1];
            kvp[n0 * 128 + m0 + 8]         = acc[t][j][2];
            kvp[(n0 + 1) * 128 + m0 + 8]   = acc[t][j][3];
        }
    // ksum: lanes with (lane&3)==0 hold column 0 of the ones-MMA result
    if ((lane & 3) == 0) {
        float* ksp = d_ksum + (seg * NHEADS_TOT + n) * 128;
        #pragma unroll
        for (int t = 0; t < 2; t++) {
            int m0 = wid * 32 + t * 16 + (lane >> 2);
            ksp[m0]     = acc_ks[t][0];
            ksp[m0 + 8] = acc_ks[t][2];
        }
    }
}

// ---------------- kv partial reduction: fp32 x NSEG -> fp16 -----------------
__global__ __launch_bounds__(256) void kvreduce_kernel() {
    int n = blockIdx.x;
    int tid = threadIdx.x;
    const float* kv0 = d_kvT + (size_t)n * 8192;
    #pragma unroll
    for (int i = 0; i < 32; i++) {
        int idx = tid + i * 256;
        float v = 0.f;
        #pragma unroll
        for (int s = 0; s < NSEG; s++)
            v += kv0[(size_t)s * NHEADS_TOT * 8192 + idx];
        d_kvTh[(size_t)n * 8192 + idx] = __float2half(v);
    }
    if (tid < 128) {
        float v = 0.f;
        #pragma unroll
        for (int s = 0; s < NSEG; s++)
            v += d_ksum[(s * NHEADS_TOT + n) * 128 + tid];
        d_ksumR[n * 128 + tid] = v;
    }
}

// ---------------- attention stage 2: HMMA out + z + residual ---------------
__global__ __launch_bounds__(128) void attn_out_kernel() {
    __shared__ __half skvT[64][136];
    __shared__ __half sq[128][136];
    __shared__ float sks[128];
    __shared__ float ssin[128], scos[128], sz[128];
    int n = blockIdx.x, lb = blockIdx.y;
    int b = n / NHEAD, hh = n % NHEAD;
    int tid = threadIdx.x, lane = tid & 31, wid = tid >> 5;
    int l0 = lb * 128;
    uint32_t sqb = smem_to_u32(sq), skvb = smem_to_u32(skvT);

    {
        const uint4* kvh = (const uint4*)(d_kvTh + (size_t)n * 8192);
        #pragma unroll
        for (int i = 0; i < 8; i++) {
            int idx4 = tid + i * 128;
            int row = idx4 >> 4, col = (idx4 & 15) * 8;
            *(uint4*)&skvT[row][col] = kvh[idx4];
        }
        sks[tid] = d_ksumR[n * 128 + tid];
    }
    {
        int l = l0 + tid;
        float s, c;
        sincosf(0.5f * CUDART_PI_F * (float)(l + 1) / (float)LSEQ, &s, &c);
        ssin[tid] = s; scos[tid] = c;
    }
    __syncthreads();

    #pragma unroll
    for (int i = 0; i < 32; i++) {
        int idx = tid + i * 128;
        int lc = idx >> 5, g = idx & 31;
        int m = (l0 + lc) * BATCH + b;
        __half2 qh = *(const __half2*)&d_Qh[(size_t)m * EMB + hh * HDIM + g * 2];
        float2 qf = __half22float2(qh);
        float s = ssin[lc], c = scos[lc];
        *(__half2*)&sq[lc][g * 2]      = __floats2half2_rn(qf.x * s, qf.y * s);
        *(__half2*)&sq[lc][64 + g * 2] = __floats2half2_rn(qf.x * c, qf.y * c);
    }
    __syncthreads();

    {
        float dp = 0.f;
        #pragma unroll 16
        for (int d = 0; d < 128; d++)
            dp += __half2float(sq[tid][d]) * sks[d];
        sz[tid] = 1.0f / fmaxf(dp, 1e-6f);
    }
    __syncthreads();

    float acc[2][8][4];
    #pragma unroll
    for (int t = 0; t < 2; t++)
        #pragma unroll
        for (int j = 0; j < 8; j++)
            #pragma unroll
            for (int i = 0; i < 4; i++) acc[t][j][i] = 0.f;

    int a_mr = lane & 15;
    int a_ks = lane >> 4;
    int b_nr = ((lane >> 4) << 3) | (lane & 7);
    int b_ks = (lane >> 3) & 1;

    #pragma unroll
    for (int kc = 0; kc < 8; kc++) {
        uint32_t ah[2][4], bb[4][4];
        #pragma unroll
        for (int t = 0; t < 2; t++)
            ldsm4(ah[t], sqb + (uint32_t)(wid * 32 + t * 16 + a_mr) * 272u + kc * 32u + a_ks * 16u);
        #pragma unroll
        for (int g = 0; g < 4; g++)
            ldsm4(bb[g], skvb + (uint32_t)(g * 16 + b_nr) * 272u + kc * 32u + b_ks * 16u);
        #pragma unroll
        for (int t = 0; t < 2; t++)
            #pragma unroll
            for (int j = 0; j < 8; j++)
                mma16816(acc[t][j], ah[t], bb[j >> 1][2 * (j & 1)], bb[j >> 1][2 * (j & 1) + 1]);
    }

    int g4 = lane >> 2, tq = lane & 3;
    #pragma unroll
    for (int t = 0; t < 2; t++) {
        #pragma unroll
        for (int j = 0; j < 8; j++) {
            int lloc = wid * 32 + t * 16 + g4;
            int dv = j * 8 + tq * 2;
            #pragma unroll
            for (int half = 0; half < 2; half++) {
                int ll = lloc + half * 8;
                float z = sz[ll];
                int m = (l0 + ll) * BATCH + b;
                int tile = (m >> 7) * KCH + hh;
                uint32_t ti = tiled_idx(tile, m & 127, dv);
                float2 xv = __half22float2(*(const __half2*)&d_Xh[ti]);
                float y0 = xv.x + z * acc[t][j][half * 2];
                float y1 = xv.y + z * acc[t][j][half * 2 + 1];
                *(__half2*)&d_Yh[ti] = __floats2half2_rn(y0, y1);
            }
        }
    }
}

// ---------------- launch ----------------
extern "C" void kernel_launch(void* const* d_in, const int* in_sizes, int n_in,
                              void* d_out, int out_size) {
    const float* query = (const float*)d_in[0];
    const float* Wq = (const float*)d_in[1];
    const float* bq = (const float*)d_in[2];
    const float* Wk = (const float*)d_in[3];
    const float* bk = (const float*)d_in[4];
    const float* Wv = (const float*)d_in[5];
    const float* bv = (const float*)d_in[6];
    const float* Wo = (const float*)d_in[7];
    const float* bo = (const float*)d_in[8];
    float* out = (float*)d_out;

    __half *pQh, *pKh, *pVh, *pXh, *pYh, *pWqkv, *pWo;
    cudaGetSymbolAddress((void**)&pQh, d_Qh);
    cudaGetSymbolAddress((void**)&pKh, d_Kh);
    cudaGetSymbolAddress((void**)&pVh, d_Vh);
    cudaGetSymbolAddress((void**)&pXh, d_Xh);
    cudaGetSymbolAddress((void**)&pYh, d_Yh);
    cudaGetSymbolAddress((void**)&pWqkv, d_Wqkv);
    cudaGetSymbolAddress((void**)&pWo, d_Wo);

    cudaFuncSetAttribute(tcgemm_kernel<0>, cudaFuncAttributeMaxDynamicSharedMemorySize, GEMM_SMEM);
    cudaFuncSetAttribute(tcgemm_kernel<1>, cudaFuncAttributeMaxDynamicSharedMemorySize, GEMM_SMEM);

    // 1: fused transpose + weight conversion
    prep_kernel<<<TRANS_BLOCKS + WCONV_BLOCKS, 256>>>(query, Wq, Wk, Wv, Wo);

    // 2: combined QKV GEMM (fp16 single product)
    tcgemm_kernel<0><<<dim3(18, MT), 128, GEMM_SMEM>>>(
        pXh, pWqkv, bq, bk, bv, pQh, pKh, pVh, 0b011);

    // 3 (ncu capture slot is 4th; keep attn_kv near): HMMA kv reduction
    attn_kv_kernel<<<dim3(NHEADS_TOT, NSEG), 128>>>();

    kvreduce_kernel<<<NHEADS_TOT, 256>>>();                              // 4

    // 5: HMMA out + z + residual
    attn_out_kernel<<<dim3(NHEADS_TOT, LSEQ / 128), 128>>>();

    // 6: O projection (fp16 single product, fp32 out)
    tcgemm_kernel<1><<<dim3(6, MT), 128, GEMM_SMEM>>>(
        pYh, pWo, bo, bo, bo, out, out, out, 0);
}